// round 6
// baseline (speedup 1.0000x reference)
#include <cuda_runtime.h>
#include <cuda_bf16.h>
#include <mma.h>
#include <math.h>
#include <stdint.h>

using namespace nvcuda;

// Problem constants
#define NN      100000
#define EMAX    1700000
#define NCLASS  40
#define SB      512
#define NB1     ((NN + SB - 1) / SB)
#define NTILE   782                    // ceil(NN/128)
#define NPAD    (NTILE * 128)          // 100096

// ---------------- scratch (static device globals) ----------------
__device__ float g_Wh1[(size_t)NPAD * 256];   // layer1 Wh fp32
__device__ float g_Wh2[(size_t)NPAD * 48];    // layer2 Wh fp32, ld=48
__device__ float g_s1r[NN * 4];
__device__ float g_s1c[NN * 4];
__device__ float g_s2r[NN];
__device__ float g_s2c[NN];
__device__ int   g_deg[NN];
__device__ int   g_cur[NN];
__device__ int   g_off[NN + 1];
__device__ int   g_csr[EMAX];
__device__ int   g_bsum[256];
__device__ int   g_boff[256];
// pre-split bf16 operands (row-major)
__device__ __align__(16) unsigned char g_xh[(size_t)NPAD * 128 * 2];
__device__ __align__(16) unsigned char g_xl[(size_t)NPAD * 128 * 2];
__device__ __align__(16) unsigned char g_hh[(size_t)NPAD * 256 * 2];
__device__ __align__(16) unsigned char g_hl[(size_t)NPAD * 256 * 2];
__device__ __align__(16) unsigned char g_B1h[128 * 256 * 2];
__device__ __align__(16) unsigned char g_B1l[128 * 256 * 2];
__device__ __align__(16) unsigned char g_B2h[256 * 48 * 2];
__device__ __align__(16) unsigned char g_B2l[256 * 48 * 2];

// ---------------- helpers ----------------
__device__ __forceinline__ uint32_t smem_u32(const void* p) {
    uint32_t a;
    asm("{ .reg .u64 t; cvta.to.shared.u64 t, %1; cvt.u32.u64 %0, t; }" : "=r"(a) : "l"(p));
    return a;
}
__device__ __forceinline__ void cpa16(uint32_t dst, const void* src) {
    asm volatile("cp.async.cg.shared.global [%0], [%1], 16;" :: "r"(dst), "l"(src));
}
#define CP_COMMIT() asm volatile("cp.async.commit_group;" ::: "memory")
#define CP_WAIT1()  asm volatile("cp.async.wait_group 1;" ::: "memory")
#define CP_WAIT0()  asm volatile("cp.async.wait_group 0;" ::: "memory")

__device__ __forceinline__ float wmax(float v) {
    #pragma unroll
    for (int o = 16; o; o >>= 1) v = fmaxf(v, __shfl_xor_sync(0xffffffffu, v, o));
    return v;
}
__device__ __forceinline__ float wsum(float v) {
    #pragma unroll
    for (int o = 16; o; o >>= 1) v += __shfl_xor_sync(0xffffffffu, v, o);
    return v;
}
__device__ __forceinline__ float lrelu(float v) { return v > 0.f ? v : 0.1f * v; }
__device__ __forceinline__ float elu(float v)   { return v > 0.f ? v : expm1f(v); }

__device__ __forceinline__ void split4(float4 v, uint2& hi, uint2& lo) {
    __nv_bfloat16 h0 = __float2bfloat16_rn(v.x), h1 = __float2bfloat16_rn(v.y),
                  h2 = __float2bfloat16_rn(v.z), h3 = __float2bfloat16_rn(v.w);
    hi.x = ((uint32_t)__bfloat16_as_ushort(h1) << 16) | __bfloat16_as_ushort(h0);
    hi.y = ((uint32_t)__bfloat16_as_ushort(h3) << 16) | __bfloat16_as_ushort(h2);
    __nv_bfloat162 l01 = __floats2bfloat162_rn(v.x - __bfloat162float(h0), v.y - __bfloat162float(h1));
    __nv_bfloat162 l23 = __floats2bfloat162_rn(v.z - __bfloat162float(h2), v.w - __bfloat162float(h3));
    lo.x = *(uint32_t*)&l01;
    lo.y = *(uint32_t*)&l23;
}

// ---------------- prep: split x and weights to bf16 hi/lo ----------------
#define XIT 3200000   // NN*128/4 float4 items
__global__ void k_prep(const float* __restrict__ x, const float* __restrict__ W,
                       const float* __restrict__ Wout) {
    int stride = gridDim.x * blockDim.x;
    for (int i = blockIdx.x * blockDim.x + threadIdx.x; i < XIT + 32768 + 12288 + 6144; i += stride) {
        if (i < XIT) {
            int r = i >> 5, kq = (i & 31) * 4;
            float4 v = __ldg((const float4*)&x[(size_t)r * 128 + kq]);
            uint2 hi, lo;
            split4(v, hi, lo);
            *(uint2*)(g_xh + ((size_t)r * 128 + kq) * 2) = hi;
            *(uint2*)(g_xl + ((size_t)r * 128 + kq) * 2) = lo;
        } else if (i < XIT + 32768) {
            int i2 = i - XIT;
            int k = i2 >> 8, n = i2 & 255;
            float v = W[(n >> 6) * 8192 + k * 64 + (n & 63)];
            __nv_bfloat16 h = __float2bfloat16_rn(v);
            __nv_bfloat16 l = __float2bfloat16_rn(v - __bfloat162float(h));
            *(__nv_bfloat16*)(g_B1h + (size_t)i2 * 2) = h;
            *(__nv_bfloat16*)(g_B1l + (size_t)i2 * 2) = l;
        } else if (i < XIT + 32768 + 12288) {
            int j = i - XIT - 32768;
            int k = j / 48, n = j - k * 48;
            float v = (n < NCLASS) ? Wout[k * NCLASS + n] : 0.f;
            __nv_bfloat16 h = __float2bfloat16_rn(v);
            __nv_bfloat16 l = __float2bfloat16_rn(v - __bfloat162float(h));
            *(__nv_bfloat16*)(g_B2h + (size_t)j * 2) = h;
            *(__nv_bfloat16*)(g_B2l + (size_t)j * 2) = l;
        } else {
            int j = i - XIT - 45056;
            uint4 z = make_uint4(0, 0, 0, 0);
            if (j < 3072) *(uint4*)(g_hh + (size_t)NN * 512 + (size_t)j * 16) = z;
            else          *(uint4*)(g_hl + (size_t)NN * 512 + (size_t)(j - 3072) * 16) = z;
        }
    }
}

// ---------------- CSR build ----------------
__global__ void k_zero() {
    int i = blockIdx.x * blockDim.x + threadIdx.x;
    if (i < NN) { g_deg[i] = 0; g_cur[i] = 0; }
}
__global__ void k_count(const int* __restrict__ row, int E) {
    int e = blockIdx.x * blockDim.x + threadIdx.x;
    if (e < E) atomicAdd(&g_deg[__ldg(&row[e])], 1);
}
__global__ void k_scan1() {
    __shared__ int s[SB];
    int tid = threadIdx.x, g = blockIdx.x * SB + tid;
    int v = (g < NN) ? g_deg[g] : 0;
    s[tid] = v; __syncthreads();
    for (int o = 1; o < SB; o <<= 1) {
        int t = (tid >= o) ? s[tid - o] : 0;
        __syncthreads(); s[tid] += t; __syncthreads();
    }
    if (g < NN) g_off[g] = s[tid] - v;
    if (tid == SB - 1) g_bsum[blockIdx.x] = s[tid];
}
__global__ void k_scan2() {
    __shared__ int s[256];
    int tid = threadIdx.x;
    int v = (tid < NB1) ? g_bsum[tid] : 0;
    s[tid] = v; __syncthreads();
    for (int o = 1; o < 256; o <<= 1) {
        int t = (tid >= o) ? s[tid - o] : 0;
        __syncthreads(); s[tid] += t; __syncthreads();
    }
    g_boff[tid] = s[tid] - v;
}
__global__ void k_scan3(int E) {
    int tid = threadIdx.x, g = blockIdx.x * SB + tid;
    if (g < NN) g_off[g] += g_boff[blockIdx.x];
    if (g == 0) g_off[NN] = E;
}
__global__ void k_fill(const int* __restrict__ row, const int* __restrict__ col, int E) {
    int e = blockIdx.x * blockDim.x + threadIdx.x;
    if (e >= E) return;
    int r = __ldg(&row[e]);
    int p = g_off[r] + atomicAdd(&g_cur[r], 1);
    g_csr[p] = __ldg(&col[e]);
}

// ---------------- GEMM1: Wh1 = x @ B1 [128x256, K=128, 512 thr, fused s1] ----------------
#define S1_AH 0
#define S1_AL 18432
#define S1_BH 36864
#define S1_BL 70656
#define S1_STAGE 104448
#define S1_BYTES (2 * S1_STAGE)

__global__ __launch_bounds__(512) void k_gemm1(const float* __restrict__ a) {
    extern __shared__ __align__(16) unsigned char smem[];
    uint32_t sbase = smem_u32(smem);
    int tid = threadIdx.x;
    int m0 = blockIdx.x * 128;

    // issue cp.async for both k-chunks
    #pragma unroll
    for (int c = 0; c < 2; c++) {
        uint32_t st = sbase + c * S1_STAGE;
        #pragma unroll
        for (int t = 0; t < 2; t++) {           // A: 1024 chunks/buffer
            int idx = tid + t * 512;
            int r = idx >> 3, c8 = idx & 7;
            size_t so = ((size_t)(m0 + r) * 128 + c * 64 + c8 * 8) * 2;
            uint32_t doff = (uint32_t)(r * 72 + c8 * 8) * 2;
            cpa16(st + S1_AH + doff, g_xh + so);
            cpa16(st + S1_AL + doff, g_xl + so);
        }
        #pragma unroll
        for (int t = 0; t < 4; t++) {           // B: 2048 chunks/buffer
            int idx = tid + t * 512;
            int kr = idx >> 5, c16 = idx & 31;
            size_t so = ((size_t)(c * 64 + kr) * 256 + c16 * 8) * 2;
            uint32_t doff = (uint32_t)(kr * 264 + c16 * 8) * 2;
            cpa16(st + S1_BH + doff, g_B1h + so);
            cpa16(st + S1_BL + doff, g_B1l + so);
        }
        CP_COMMIT();
    }

    int wid = tid >> 5, wm = wid & 3, wn = wid >> 2;  // 4M x 4N warps, tile 32x64

    wmma::fragment<wmma::accumulator, 16, 16, 16, float> acc[2][4];
    #pragma unroll
    for (int i = 0; i < 2; i++)
        #pragma unroll
        for (int j = 0; j < 4; j++) wmma::fill_fragment(acc[i][j], 0.f);

    CP_WAIT1();
    __syncthreads();

    #pragma unroll
    for (int c = 0; c < 2; c++) {
        const unsigned char* st = smem + c * S1_STAGE;
        #pragma unroll
        for (int pass = 0; pass < 3; pass++) {
            const __nv_bfloat16* A_ = (const __nv_bfloat16*)(st + (pass == 2 ? S1_AL : S1_AH));
            const __nv_bfloat16* B_ = (const __nv_bfloat16*)(st + (pass == 1 ? S1_BL : S1_BH));
            #pragma unroll
            for (int k8 = 0; k8 < 4; k8++) {
                wmma::fragment<wmma::matrix_a, 16, 16, 16, __nv_bfloat16, wmma::row_major> af[2];
                wmma::fragment<wmma::matrix_b, 16, 16, 16, __nv_bfloat16, wmma::row_major> bfr[4];
                #pragma unroll
                for (int i = 0; i < 2; i++)
                    wmma::load_matrix_sync(af[i], A_ + (wm * 32 + i * 16) * 72 + k8 * 16, 72);
                #pragma unroll
                for (int j = 0; j < 4; j++)
                    wmma::load_matrix_sync(bfr[j], B_ + (k8 * 16) * 264 + wn * 64 + j * 16, 264);
                #pragma unroll
                for (int i = 0; i < 2; i++)
                    #pragma unroll
                    for (int j = 0; j < 4; j++)
                        wmma::mma_sync(acc[i][j], af[i], bfr[j], acc[i][j]);
            }
        }
        if (c == 0) { CP_WAIT0(); __syncthreads(); }
    }

    // epilogue: stage output tile in smem (ld 264), then copy + fused s1
    __syncthreads();
    float* tile = (float*)smem;
    #pragma unroll
    for (int i = 0; i < 2; i++)
        #pragma unroll
        for (int j = 0; j < 4; j++)
            wmma::store_matrix_sync(&tile[(wm * 32 + i * 16) * 264 + wn * 64 + j * 16],
                                    acc[i][j], 264, wmma::mem_row_major);
    __syncthreads();

    // copy tile -> g_Wh1 (8192 float4)
    #pragma unroll
    for (int t = 0; t < 16; t++) {
        int idx = tid + t * 512;
        int r = idx >> 6, c4 = idx & 63;
        float4 v = *(const float4*)&tile[r * 264 + c4 * 4];
        *(float4*)&g_Wh1[(size_t)(m0 + r) * 256 + c4 * 4] = v;
    }
    // fused s1: thread (row, head) computes full dots over this head's 64 cols
    {
        int row = tid >> 2, h = tid & 3;
        const float* rp = &tile[row * 264 + h * 64];
        float sr = 0.f, sc = 0.f;
        #pragma unroll
        for (int j = 0; j < 64; j++) {
            float v = rp[j];
            sr += v * __ldg(&a[h * 128 + j]);
            sc += v * __ldg(&a[h * 128 + 64 + j]);
        }
        int gr = m0 + row;
        if (gr < NN) {
            g_s1r[gr * 4 + h] = sr;
            g_s1c[gr * 4 + h] = sc;
        }
    }
}

// ---------------- GEMM2: Wh2 = h @ B2 [128x48, K=256, fused s2] ----------------
#define S2_AH 0
#define S2_AL 34816
#define S2_BH 69632
#define S2_BL 83968
#define S2_STAGE 98304
#define S2_BYTES (2 * S2_STAGE)

__global__ __launch_bounds__(256) void k_gemm2(const float* __restrict__ aout) {
    extern __shared__ __align__(16) unsigned char smem[];
    uint32_t sbase = smem_u32(smem);
    int tid = threadIdx.x;
    int m0 = blockIdx.x * 128;

    #pragma unroll
    for (int c = 0; c < 2; c++) {
        uint32_t st = sbase + c * S2_STAGE;
        #pragma unroll
        for (int t = 0; t < 8; t++) {           // A: 2048 chunks/buffer
            int idx = tid + t * 256;
            int r = idx >> 4, c16 = idx & 15;
            size_t so = ((size_t)(m0 + r) * 256 + c * 128 + c16 * 8) * 2;
            uint32_t doff = (uint32_t)(r * 136 + c16 * 8) * 2;
            cpa16(st + S2_AH + doff, g_hh + so);
            cpa16(st + S2_AL + doff, g_hl + so);
        }
        #pragma unroll
        for (int t = 0; t < 3; t++) {           // B: 768 chunks/buffer
            int idx = tid + t * 256;
            int kr = idx / 6, c6 = idx - kr * 6;
            size_t so = ((size_t)(c * 128 + kr) * 48 + c6 * 8) * 2;
            uint32_t doff = (uint32_t)(kr * 56 + c6 * 8) * 2;
            cpa16(st + S2_BH + doff, g_B2h + so);
            cpa16(st + S2_BL + doff, g_B2l + so);
        }
        CP_COMMIT();
    }

    int wid = tid >> 5;                          // warp tile 16 x 48

    wmma::fragment<wmma::accumulator, 16, 16, 16, float> acc[3];
    #pragma unroll
    for (int j = 0; j < 3; j++) wmma::fill_fragment(acc[j], 0.f);

    CP_WAIT1();
    __syncthreads();

    #pragma unroll
    for (int c = 0; c < 2; c++) {
        const unsigned char* st = smem + c * S2_STAGE;
        #pragma unroll
        for (int pass = 0; pass < 3; pass++) {
            const __nv_bfloat16* A_ = (const __nv_bfloat16*)(st + (pass == 2 ? S2_AL : S2_AH));
            const __nv_bfloat16* B_ = (const __nv_bfloat16*)(st + (pass == 1 ? S2_BL : S2_BH));
            #pragma unroll
            for (int k16 = 0; k16 < 8; k16++) {
                wmma::fragment<wmma::matrix_a, 16, 16, 16, __nv_bfloat16, wmma::row_major> af;
                wmma::fragment<wmma::matrix_b, 16, 16, 16, __nv_bfloat16, wmma::row_major> bfr[3];
                wmma::load_matrix_sync(af, A_ + (wid * 16) * 136 + k16 * 16, 136);
                #pragma unroll
                for (int j = 0; j < 3; j++)
                    wmma::load_matrix_sync(bfr[j], B_ + (k16 * 16) * 56 + j * 16, 56);
                #pragma unroll
                for (int j = 0; j < 3; j++)
                    wmma::mma_sync(acc[j], af, bfr[j], acc[j]);
            }
        }
        if (c == 0) { CP_WAIT0(); __syncthreads(); }
    }

    // epilogue: stage in smem (ld 56), copy + fused s2
    __syncthreads();
    float* tile = (float*)smem;
    #pragma unroll
    for (int j = 0; j < 3; j++)
        wmma::store_matrix_sync(&tile[(wid * 16) * 56 + j * 16], acc[j], 56, wmma::mem_row_major);
    __syncthreads();

    #pragma unroll
    for (int t = 0; t < 6; t++) {               // 1536 float4
        int idx = tid + t * 256;
        int r = idx / 12, c4 = idx - r * 12;
        float4 v = *(const float4*)&tile[r * 56 + c4 * 4];
        *(float4*)&g_Wh2[(size_t)(m0 + r) * 48 + c4 * 4] = v;
    }
    if (tid < 128) {
        int row = tid;
        const float* rp = &tile[row * 56];
        float sr = 0.f, sc = 0.f;
        #pragma unroll
        for (int j = 0; j < 40; j++) {
            float v = rp[j];
            sr += v * __ldg(&aout[j]);
            sc += v * __ldg(&aout[40 + j]);
        }
        int gr = m0 + row;
        if (gr < NN) { g_s2r[gr] = sr; g_s2c[gr] = sc; }
    }
}

// ---------------- layer1 aggregation (warp per node); emits h as bf16 hi/lo ----------------
__global__ void k_gat1() {
    int gw = (blockIdx.x * blockDim.x + threadIdx.x) >> 5;
    int lane = threadIdx.x & 31;
    if (gw >= NN) return;
    const float4 sr = *(const float4*)&g_s1r[gw * 4];
    int beg = g_off[gw], end = g_off[gw + 1];

    float4 acc0 = make_float4(0.f, 0.f, 0.f, 0.f);
    float4 acc1 = make_float4(0.f, 0.f, 0.f, 0.f);
    float d0 = 0.f, d1 = 0.f, d2 = 0.f, d3 = 0.f;

    for (int base = beg; base < end; base += 32) {
        int e = base + lane;
        int j = 0; float ex0 = 0.f, ex1 = 0.f, ex2 = 0.f, ex3 = 0.f;
        if (e < end) {
            j = __ldg(&g_csr[e]);
            float4 s = __ldg((const float4*)&g_s1c[j * 4]);
            ex0 = __expf(lrelu(sr.x + s.x));
            ex1 = __expf(lrelu(sr.y + s.y));
            ex2 = __expf(lrelu(sr.z + s.z));
            ex3 = __expf(lrelu(sr.w + s.w));
            d0 += ex0; d1 += ex1; d2 += ex2; d3 += ex3;
        }
        int cnt = min(32, end - base);
        for (int k = 0; k < cnt; k++) {
            int   jj = __shfl_sync(0xffffffffu, j,   k);
            float w0 = __shfl_sync(0xffffffffu, ex0, k);
            float w1 = __shfl_sync(0xffffffffu, ex1, k);
            float w2 = __shfl_sync(0xffffffffu, ex2, k);
            float w3 = __shfl_sync(0xffffffffu, ex3, k);
            const float* wp = &g_Wh1[(size_t)jj * 256];
            float4 v0 = __ldg((const float4*)&wp[4 * lane]);
            float4 v1 = __ldg((const float4*)&wp[128 + 4 * lane]);
            float wa = (lane < 16) ? w0 : w1;
            float wb = (lane < 16) ? w2 : w3;
            acc0.x += wa * v0.x; acc0.y += wa * v0.y; acc0.z += wa * v0.z; acc0.w += wa * v0.w;
            acc1.x += wb * v1.x; acc1.y += wb * v1.y; acc1.z += wb * v1.z; acc1.w += wb * v1.w;
        }
    }
    d0 = wsum(d0); d1 = wsum(d1); d2 = wsum(d2); d3 = wsum(d3);
    float inva = (lane < 16) ? (1.f / d0) : (1.f / d1);
    float invb = (lane < 16) ? (1.f / d2) : (1.f / d3);

    float4 r0 = make_float4(elu(acc0.x * inva), elu(acc0.y * inva),
                            elu(acc0.z * inva), elu(acc0.w * inva));
    float4 r1 = make_float4(elu(acc1.x * invb), elu(acc1.y * invb),
                            elu(acc1.z * invb), elu(acc1.w * invb));
    uint2 h0, l0, h1, l1;
    split4(r0, h0, l0);
    split4(r1, h1, l1);
    size_t o0 = ((size_t)gw * 256 + 4 * lane) * 2;
    size_t o1 = ((size_t)gw * 256 + 128 + 4 * lane) * 2;
    *(uint2*)(g_hh + o0) = h0;
    *(uint2*)(g_hl + o0) = l0;
    *(uint2*)(g_hh + o1) = h1;
    *(uint2*)(g_hl + o1) = l1;
}

// ---------------- layer2 attention + ELU + log_softmax ----------------
__global__ void k_gat2(float* __restrict__ out) {
    int gw = (blockIdx.x * blockDim.x + threadIdx.x) >> 5;
    int lane = threadIdx.x & 31;
    if (gw >= NN) return;
    float s2v = __ldg(&g_s2r[gw]);
    int beg = g_off[gw], end = g_off[gw + 1];
    int half = lane >> 4, sl = lane & 15;

    float4 acc = make_float4(0.f, 0.f, 0.f, 0.f);
    float den = 0.f;
    for (int base = beg; base < end; base += 32) {
        int e = base + lane;
        int j = 0; float ex = 0.f;
        if (e < end) {
            j = __ldg(&g_csr[e]);
            ex = __expf(lrelu(s2v + __ldg(&g_s2c[j])));
            den += ex;
        }
        int cnt = min(32, end - base);
        for (int k = 0; k < cnt; k += 2) {
            int kk = k + half;
            int src = (kk < cnt) ? kk : k;
            int   jj = __shfl_sync(0xffffffffu, j,  src);
            float w  = __shfl_sync(0xffffffffu, ex, src);
            if (kk >= cnt) w = 0.f;
            if (sl < 10) {
                float4 v = __ldg((const float4*)&g_Wh2[(size_t)jj * 48 + 4 * sl]);
                acc.x += w * v.x; acc.y += w * v.y; acc.z += w * v.z; acc.w += w * v.w;
            }
        }
    }
    acc.x += __shfl_xor_sync(0xffffffffu, acc.x, 16);
    acc.y += __shfl_xor_sync(0xffffffffu, acc.y, 16);
    acc.z += __shfl_xor_sync(0xffffffffu, acc.z, 16);
    acc.w += __shfl_xor_sync(0xffffffffu, acc.w, 16);
    den = wsum(den);
    float inv = 1.f / den;
    bool valid = (lane < 10);
    float o0 = -1e30f, o1 = -1e30f, o2 = -1e30f, o3 = -1e30f;
    if (valid) {
        o0 = elu(acc.x * inv); o1 = elu(acc.y * inv);
        o2 = elu(acc.z * inv); o3 = elu(acc.w * inv);
    }
    float mm = wmax(fmaxf(fmaxf(o0, o1), fmaxf(o2, o3)));
    float se = 0.f;
    if (valid) se = __expf(o0 - mm) + __expf(o1 - mm) + __expf(o2 - mm) + __expf(o3 - mm);
    se = wsum(se);
    float L = mm + logf(se);
    if (valid)
        *(float4*)&out[(size_t)gw * NCLASS + 4 * lane] = make_float4(o0 - L, o1 - L, o2 - L, o3 - L);
}

// ---------------- launch ----------------
extern "C" void kernel_launch(void* const* d_in, const int* in_sizes, int n_in,
                              void* d_out, int out_size) {
    const float* x    = (const float*)d_in[0];
    const float* W    = (const float*)d_in[1];
    const float* a    = (const float*)d_in[2];
    const float* Wout = (const float*)d_in[3];
    const float* aout = (const float*)d_in[4];
    const int*   row  = (const int*)d_in[5];
    const int*   col  = (const int*)d_in[6];
    int E = in_sizes[5];
    float* out = (float*)d_out;

    static cudaStream_t s2 = nullptr;
    static cudaEvent_t evF = nullptr, evJ = nullptr;
    if (!s2) {
        cudaStreamCreateWithFlags(&s2, cudaStreamNonBlocking);
        cudaEventCreateWithFlags(&evF, cudaEventDisableTiming);
        cudaEventCreateWithFlags(&evJ, cudaEventDisableTiming);
        cudaFuncSetAttribute(k_gemm1, cudaFuncAttributeMaxDynamicSharedMemorySize, S1_BYTES);
        cudaFuncSetAttribute(k_gemm2, cudaFuncAttributeMaxDynamicSharedMemorySize, S2_BYTES);
    }

    // fork CSR chain immediately
    cudaEventRecord(evF, 0);
    cudaStreamWaitEvent(s2, evF, 0);
    k_zero <<<(NN + 255) / 256, 256, 0, s2>>>();
    k_count<<<(E + 255) / 256, 256, 0, s2>>>(row, E);

    k_prep<<<1280, 256>>>(x, W, Wout);
    k_gemm1<<<NTILE, 512, S1_BYTES>>>(a);              // profiled slot

    k_scan1<<<NB1, SB, 0, s2>>>();
    k_scan2<<<1, 256, 0, s2>>>();
    k_scan3<<<NB1, SB, 0, s2>>>(E);
    k_fill <<<(E + 255) / 256, 256, 0, s2>>>(row, col, E);

    cudaEventRecord(evJ, s2);
    cudaStreamWaitEvent(0, evJ, 0);

    k_gat1<<<(NN + 7) / 8, 256>>>();
    k_gemm2<<<NTILE, 256, S2_BYTES>>>(aout);
    k_gat2<<<(NN + 7) / 8, 256>>>(out);
}

// round 7
// speedup vs baseline: 1.2322x; 1.2322x over previous
#include <cuda_runtime.h>
#include <cuda_bf16.h>
#include <cuda_fp16.h>
#include <mma.h>
#include <math.h>
#include <stdint.h>

using namespace nvcuda;

// Problem constants
#define NN      100000
#define EMAX    1700000
#define NCLASS  40
#define SB      512
#define NB1     ((NN + SB - 1) / SB)
#define NTILE   782                    // ceil(NN/128)
#define NPAD    (NTILE * 128)          // 100096

// ---------------- scratch (static device globals) ----------------
__device__ __align__(16) __half g_Wh1h[(size_t)NPAD * 256];  // layer1 Wh fp16 (gather source)
__device__ float g_Wh2[(size_t)NPAD * 48];    // layer2 Wh fp32, ld=48
__device__ float g_s1r[NN * 4];
__device__ float g_s1c[NN * 4];
__device__ float g_s2r[NN];
__device__ float g_s2c[NN];
__device__ int   g_deg[NN];
__device__ int   g_cur[NN];
__device__ int   g_off[NN + 1];
__device__ int   g_csr[EMAX];
__device__ int   g_bsum[256];
__device__ int   g_boff[256];
// pre-split bf16 operands (row-major)
__device__ __align__(16) unsigned char g_xh[(size_t)NPAD * 128 * 2];
__device__ __align__(16) unsigned char g_xl[(size_t)NPAD * 128 * 2];
__device__ __align__(16) unsigned char g_hh[(size_t)NPAD * 256 * 2];
__device__ __align__(16) unsigned char g_hl[(size_t)NPAD * 256 * 2];
__device__ __align__(16) unsigned char g_B1h[128 * 256 * 2];
__device__ __align__(16) unsigned char g_B1l[128 * 256 * 2];
__device__ __align__(16) unsigned char g_B2h[256 * 48 * 2];
__device__ __align__(16) unsigned char g_B2l[256 * 48 * 2];

// ---------------- helpers ----------------
__device__ __forceinline__ uint32_t smem_u32(const void* p) {
    uint32_t a;
    asm("{ .reg .u64 t; cvta.to.shared.u64 t, %1; cvt.u32.u64 %0, t; }" : "=r"(a) : "l"(p));
    return a;
}
__device__ __forceinline__ void cpa16(uint32_t dst, const void* src) {
    asm volatile("cp.async.cg.shared.global [%0], [%1], 16;" :: "r"(dst), "l"(src));
}
#define CP_COMMIT() asm volatile("cp.async.commit_group;" ::: "memory")
#define CP_WAIT1()  asm volatile("cp.async.wait_group 1;" ::: "memory")
#define CP_WAIT0()  asm volatile("cp.async.wait_group 0;" ::: "memory")

__device__ __forceinline__ float wmax(float v) {
    #pragma unroll
    for (int o = 16; o; o >>= 1) v = fmaxf(v, __shfl_xor_sync(0xffffffffu, v, o));
    return v;
}
__device__ __forceinline__ float wsum(float v) {
    #pragma unroll
    for (int o = 16; o; o >>= 1) v += __shfl_xor_sync(0xffffffffu, v, o);
    return v;
}
__device__ __forceinline__ float lrelu(float v) { return v > 0.f ? v : 0.1f * v; }
__device__ __forceinline__ float elu(float v)   { return v > 0.f ? v : expm1f(v); }

__device__ __forceinline__ void split4(float4 v, uint2& hi, uint2& lo) {
    __nv_bfloat16 h0 = __float2bfloat16_rn(v.x), h1 = __float2bfloat16_rn(v.y),
                  h2 = __float2bfloat16_rn(v.z), h3 = __float2bfloat16_rn(v.w);
    hi.x = ((uint32_t)__bfloat16_as_ushort(h1) << 16) | __bfloat16_as_ushort(h0);
    hi.y = ((uint32_t)__bfloat16_as_ushort(h3) << 16) | __bfloat16_as_ushort(h2);
    __nv_bfloat162 l01 = __floats2bfloat162_rn(v.x - __bfloat162float(h0), v.y - __bfloat162float(h1));
    __nv_bfloat162 l23 = __floats2bfloat162_rn(v.z - __bfloat162float(h2), v.w - __bfloat162float(h3));
    lo.x = *(uint32_t*)&l01;
    lo.y = *(uint32_t*)&l23;
}

// ---------------- prep: split x and weights to bf16 hi/lo ----------------
#define XIT 3200000   // NN*128/4 float4 items
__global__ void k_prep(const float* __restrict__ x, const float* __restrict__ W,
                       const float* __restrict__ Wout) {
    int stride = gridDim.x * blockDim.x;
    for (int i = blockIdx.x * blockDim.x + threadIdx.x; i < XIT + 32768 + 12288 + 6144; i += stride) {
        if (i < XIT) {
            int r = i >> 5, kq = (i & 31) * 4;
            float4 v = __ldg((const float4*)&x[(size_t)r * 128 + kq]);
            uint2 hi, lo;
            split4(v, hi, lo);
            *(uint2*)(g_xh + ((size_t)r * 128 + kq) * 2) = hi;
            *(uint2*)(g_xl + ((size_t)r * 128 + kq) * 2) = lo;
        } else if (i < XIT + 32768) {
            int i2 = i - XIT;
            int k = i2 >> 8, n = i2 & 255;
            float v = W[(n >> 6) * 8192 + k * 64 + (n & 63)];
            __nv_bfloat16 h = __float2bfloat16_rn(v);
            __nv_bfloat16 l = __float2bfloat16_rn(v - __bfloat162float(h));
            *(__nv_bfloat16*)(g_B1h + (size_t)i2 * 2) = h;
            *(__nv_bfloat16*)(g_B1l + (size_t)i2 * 2) = l;
        } else if (i < XIT + 32768 + 12288) {
            int j = i - XIT - 32768;
            int k = j / 48, n = j - k * 48;
            float v = (n < NCLASS) ? Wout[k * NCLASS + n] : 0.f;
            __nv_bfloat16 h = __float2bfloat16_rn(v);
            __nv_bfloat16 l = __float2bfloat16_rn(v - __bfloat162float(h));
            *(__nv_bfloat16*)(g_B2h + (size_t)j * 2) = h;
            *(__nv_bfloat16*)(g_B2l + (size_t)j * 2) = l;
        } else {
            int j = i - XIT - 45056;
            uint4 z = make_uint4(0, 0, 0, 0);
            if (j < 3072) *(uint4*)(g_hh + (size_t)NN * 512 + (size_t)j * 16) = z;
            else          *(uint4*)(g_hl + (size_t)NN * 512 + (size_t)(j - 3072) * 16) = z;
        }
    }
}

// ---------------- CSR build ----------------
__global__ void k_zero() {
    int i = blockIdx.x * blockDim.x + threadIdx.x;
    if (i < NN) { g_deg[i] = 0; g_cur[i] = 0; }
}
__global__ void k_count(const int* __restrict__ row, int E) {
    int e = blockIdx.x * blockDim.x + threadIdx.x;
    if (e < E) atomicAdd(&g_deg[__ldg(&row[e])], 1);
}
__global__ void k_scan1() {
    __shared__ int s[SB];
    int tid = threadIdx.x, g = blockIdx.x * SB + tid;
    int v = (g < NN) ? g_deg[g] : 0;
    s[tid] = v; __syncthreads();
    for (int o = 1; o < SB; o <<= 1) {
        int t = (tid >= o) ? s[tid - o] : 0;
        __syncthreads(); s[tid] += t; __syncthreads();
    }
    if (g < NN) g_off[g] = s[tid] - v;
    if (tid == SB - 1) g_bsum[blockIdx.x] = s[tid];
}
__global__ void k_scan2() {
    __shared__ int s[256];
    int tid = threadIdx.x;
    int v = (tid < NB1) ? g_bsum[tid] : 0;
    s[tid] = v; __syncthreads();
    for (int o = 1; o < 256; o <<= 1) {
        int t = (tid >= o) ? s[tid - o] : 0;
        __syncthreads(); s[tid] += t; __syncthreads();
    }
    g_boff[tid] = s[tid] - v;
}
__global__ void k_scan3(int E) {
    int tid = threadIdx.x, g = blockIdx.x * SB + tid;
    if (g < NN) g_off[g] += g_boff[blockIdx.x];
    if (g == 0) g_off[NN] = E;
}
__global__ void k_fill(const int* __restrict__ row, const int* __restrict__ col, int E) {
    int e = blockIdx.x * blockDim.x + threadIdx.x;
    if (e >= E) return;
    int r = __ldg(&row[e]);
    int p = g_off[r] + atomicAdd(&g_cur[r], 1);
    g_csr[p] = __ldg(&col[e]);
}

// ---------------- GEMM1: Wh1 = x @ B1 [128x256, K=128, 256 thr, 64x64 warp tiles, fused s1] ----------------
#define S1_AH 0
#define S1_AL 18432
#define S1_BH 36864
#define S1_BL 70656
#define S1_STAGE 104448
#define S1_BYTES (2 * S1_STAGE)

__global__ __launch_bounds__(256) void k_gemm1(const float* __restrict__ a) {
    extern __shared__ __align__(16) unsigned char smem[];
    uint32_t sbase = smem_u32(smem);
    int tid = threadIdx.x;
    int m0 = blockIdx.x * 128;

    // issue cp.async for both k-chunks
    #pragma unroll
    for (int c = 0; c < 2; c++) {
        uint32_t st = sbase + c * S1_STAGE;
        #pragma unroll
        for (int t = 0; t < 4; t++) {           // A: 1024 chunks/buffer
            int idx = tid + t * 256;
            int r = idx >> 3, c8 = idx & 7;
            size_t so = ((size_t)(m0 + r) * 128 + c * 64 + c8 * 8) * 2;
            uint32_t doff = (uint32_t)(r * 72 + c8 * 8) * 2;
            cpa16(st + S1_AH + doff, g_xh + so);
            cpa16(st + S1_AL + doff, g_xl + so);
        }
        #pragma unroll
        for (int t = 0; t < 8; t++) {           // B: 2048 chunks/buffer
            int idx = tid + t * 256;
            int kr = idx >> 5, c16 = idx & 31;
            size_t so = ((size_t)(c * 64 + kr) * 256 + c16 * 8) * 2;
            uint32_t doff = (uint32_t)(kr * 264 + c16 * 8) * 2;
            cpa16(st + S1_BH + doff, g_B1h + so);
            cpa16(st + S1_BL + doff, g_B1l + so);
        }
        CP_COMMIT();
    }

    int wid = tid >> 5, wm = wid & 1, wn = wid >> 1;  // 2M x 4N warps, tile 64x64

    wmma::fragment<wmma::accumulator, 16, 16, 16, float> acc[4][4];
    #pragma unroll
    for (int i = 0; i < 4; i++)
        #pragma unroll
        for (int j = 0; j < 4; j++) wmma::fill_fragment(acc[i][j], 0.f);

    CP_WAIT1();
    __syncthreads();

    #pragma unroll
    for (int c = 0; c < 2; c++) {
        const unsigned char* st = smem + c * S1_STAGE;
        #pragma unroll
        for (int pass = 0; pass < 3; pass++) {
            const __nv_bfloat16* A_ = (const __nv_bfloat16*)(st + (pass == 2 ? S1_AL : S1_AH));
            const __nv_bfloat16* B_ = (const __nv_bfloat16*)(st + (pass == 1 ? S1_BL : S1_BH));
            #pragma unroll
            for (int k8 = 0; k8 < 4; k8++) {
                wmma::fragment<wmma::matrix_a, 16, 16, 16, __nv_bfloat16, wmma::row_major> af[4];
                wmma::fragment<wmma::matrix_b, 16, 16, 16, __nv_bfloat16, wmma::row_major> bfr[4];
                #pragma unroll
                for (int i = 0; i < 4; i++)
                    wmma::load_matrix_sync(af[i], A_ + (wm * 64 + i * 16) * 72 + k8 * 16, 72);
                #pragma unroll
                for (int j = 0; j < 4; j++)
                    wmma::load_matrix_sync(bfr[j], B_ + (k8 * 16) * 264 + wn * 64 + j * 16, 264);
                #pragma unroll
                for (int i = 0; i < 4; i++)
                    #pragma unroll
                    for (int j = 0; j < 4; j++)
                        wmma::mma_sync(acc[i][j], af[i], bfr[j], acc[i][j]);
            }
        }
        if (c == 0) { CP_WAIT0(); __syncthreads(); }
    }

    // epilogue: stage fp32 tile in smem (ld 264), write fp16 Wh1, fused s1
    __syncthreads();
    float* tile = (float*)smem;
    #pragma unroll
    for (int i = 0; i < 4; i++)
        #pragma unroll
        for (int j = 0; j < 4; j++)
            wmma::store_matrix_sync(&tile[(wm * 64 + i * 16) * 264 + wn * 64 + j * 16],
                                    acc[i][j], 264, wmma::mem_row_major);
    __syncthreads();

    // fp16 write: 8192 float4 -> half4
    #pragma unroll
    for (int t = 0; t < 32; t++) {
        int idx = tid + t * 256;
        int r = idx >> 6, c4 = idx & 63;
        float4 v = *(const float4*)&tile[r * 264 + c4 * 4];
        __half2 p0 = __floats2half2_rn(v.x, v.y);
        __half2 p1 = __floats2half2_rn(v.z, v.w);
        uint2 o = make_uint2(*(uint32_t*)&p0, *(uint32_t*)&p1);
        *(uint2*)&g_Wh1h[(size_t)(m0 + r) * 256 + c4 * 4] = o;
    }
    // fused s1: thread handles (row, head) for rows tid>>2 and tid>>2 + 64
    {
        int h = tid & 3;
        #pragma unroll
        for (int rr = 0; rr < 2; rr++) {
            int row = (tid >> 2) + rr * 64;
            const float* rp = &tile[row * 264 + h * 64];
            float sr = 0.f, sc = 0.f;
            #pragma unroll
            for (int jx = 0; jx < 64; jx++) {
                int j = (h * 16 + jx) & 63;       // rotate start to reduce bank conflicts
                float v = rp[j];
                sr += v * __ldg(&a[h * 128 + j]);
                sc += v * __ldg(&a[h * 128 + 64 + j]);
            }
            int gr = m0 + row;
            if (gr < NN) {
                g_s1r[gr * 4 + h] = sr;
                g_s1c[gr * 4 + h] = sc;
            }
        }
    }
}

// ---------------- GEMM2: Wh2 = h @ B2 [128x48, K=256, fused s2] ----------------
#define S2_AH 0
#define S2_AL 34816
#define S2_BH 69632
#define S2_BL 83968
#define S2_STAGE 98304
#define S2_BYTES (2 * S2_STAGE)

__global__ __launch_bounds__(256) void k_gemm2(const float* __restrict__ aout) {
    extern __shared__ __align__(16) unsigned char smem[];
    uint32_t sbase = smem_u32(smem);
    int tid = threadIdx.x;
    int m0 = blockIdx.x * 128;

    #pragma unroll
    for (int c = 0; c < 2; c++) {
        uint32_t st = sbase + c * S2_STAGE;
        #pragma unroll
        for (int t = 0; t < 8; t++) {           // A: 2048 chunks/buffer
            int idx = tid + t * 256;
            int r = idx >> 4, c16 = idx & 15;
            size_t so = ((size_t)(m0 + r) * 256 + c * 128 + c16 * 8) * 2;
            uint32_t doff = (uint32_t)(r * 136 + c16 * 8) * 2;
            cpa16(st + S2_AH + doff, g_hh + so);
            cpa16(st + S2_AL + doff, g_hl + so);
        }
        #pragma unroll
        for (int t = 0; t < 3; t++) {           // B: 768 chunks/buffer
            int idx = tid + t * 256;
            int kr = idx / 6, c6 = idx - kr * 6;
            size_t so = ((size_t)(c * 128 + kr) * 48 + c6 * 8) * 2;
            uint32_t doff = (uint32_t)(kr * 56 + c6 * 8) * 2;
            cpa16(st + S2_BH + doff, g_B2h + so);
            cpa16(st + S2_BL + doff, g_B2l + so);
        }
        CP_COMMIT();
    }

    int wid = tid >> 5;                          // warp tile 16 x 48

    wmma::fragment<wmma::accumulator, 16, 16, 16, float> acc[3];
    #pragma unroll
    for (int j = 0; j < 3; j++) wmma::fill_fragment(acc[j], 0.f);

    CP_WAIT1();
    __syncthreads();

    #pragma unroll
    for (int c = 0; c < 2; c++) {
        const unsigned char* st = smem + c * S2_STAGE;
        #pragma unroll
        for (int pass = 0; pass < 3; pass++) {
            const __nv_bfloat16* A_ = (const __nv_bfloat16*)(st + (pass == 2 ? S2_AL : S2_AH));
            const __nv_bfloat16* B_ = (const __nv_bfloat16*)(st + (pass == 1 ? S2_BL : S2_BH));
            #pragma unroll
            for (int k16 = 0; k16 < 8; k16++) {
                wmma::fragment<wmma::matrix_a, 16, 16, 16, __nv_bfloat16, wmma::row_major> af;
                wmma::fragment<wmma::matrix_b, 16, 16, 16, __nv_bfloat16, wmma::row_major> bfr[3];
                wmma::load_matrix_sync(af, A_ + (wid * 16) * 136 + k16 * 16, 136);
                #pragma unroll
                for (int j = 0; j < 3; j++)
                    wmma::load_matrix_sync(bfr[j], B_ + (k16 * 16) * 56 + j * 16, 56);
                #pragma unroll
                for (int j = 0; j < 3; j++)
                    wmma::mma_sync(acc[j], af, bfr[j], acc[j]);
            }
        }
        if (c == 0) { CP_WAIT0(); __syncthreads(); }
    }

    // epilogue: stage in smem (ld 56), copy + fused s2
    __syncthreads();
    float* tile = (float*)smem;
    #pragma unroll
    for (int j = 0; j < 3; j++)
        wmma::store_matrix_sync(&tile[(wid * 16) * 56 + j * 16], acc[j], 56, wmma::mem_row_major);
    __syncthreads();

    #pragma unroll
    for (int t = 0; t < 6; t++) {               // 1536 float4
        int idx = tid + t * 256;
        int r = idx / 12, c4 = idx - r * 12;
        float4 v = *(const float4*)&tile[r * 56 + c4 * 4];
        *(float4*)&g_Wh2[(size_t)(m0 + r) * 48 + c4 * 4] = v;
    }
    if (tid < 128) {
        int row = tid;
        const float* rp = &tile[row * 56];
        float sr = 0.f, sc = 0.f;
        #pragma unroll
        for (int j = 0; j < 40; j++) {
            float v = rp[j];
            sr += v * __ldg(&aout[j]);
            sc += v * __ldg(&aout[40 + j]);
        }
        int gr = m0 + row;
        if (gr < NN) { g_s2r[gr] = sr; g_s2c[gr] = sc; }
    }
}

// ---------------- layer1 aggregation (warp per node, fp16 gathers); emits h as bf16 hi/lo ----------------
__global__ void k_gat1() {
    int gw = (blockIdx.x * blockDim.x + threadIdx.x) >> 5;
    int lane = threadIdx.x & 31;
    if (gw >= NN) return;
    const float4 sr = *(const float4*)&g_s1r[gw * 4];
    int beg = g_off[gw], end = g_off[gw + 1];

    float4 acc0 = make_float4(0.f, 0.f, 0.f, 0.f);
    float4 acc1 = make_float4(0.f, 0.f, 0.f, 0.f);
    float d0 = 0.f, d1 = 0.f, d2 = 0.f, d3 = 0.f;

    for (int base = beg; base < end; base += 32) {
        int e = base + lane;
        int j = 0; float ex0 = 0.f, ex1 = 0.f, ex2 = 0.f, ex3 = 0.f;
        if (e < end) {
            j = __ldg(&g_csr[e]);
            float4 s = __ldg((const float4*)&g_s1c[j * 4]);
            ex0 = __expf(lrelu(sr.x + s.x));
            ex1 = __expf(lrelu(sr.y + s.y));
            ex2 = __expf(lrelu(sr.z + s.z));
            ex3 = __expf(lrelu(sr.w + s.w));
            d0 += ex0; d1 += ex1; d2 += ex2; d3 += ex3;
        }
        int cnt = min(32, end - base);
        for (int k = 0; k < cnt; k++) {
            int   jj = __shfl_sync(0xffffffffu, j,   k);
            float w0 = __shfl_sync(0xffffffffu, ex0, k);
            float w1 = __shfl_sync(0xffffffffu, ex1, k);
            float w2 = __shfl_sync(0xffffffffu, ex2, k);
            float w3 = __shfl_sync(0xffffffffu, ex3, k);
            const __half* wp = &g_Wh1h[(size_t)jj * 256];
            uint2 q0 = __ldg((const uint2*)(wp + 4 * lane));
            uint2 q1 = __ldg((const uint2*)(wp + 128 + 4 * lane));
            float2 f0 = __half22float2(*(__half2*)&q0.x);
            float2 f1 = __half22float2(*(__half2*)&q0.y);
            float2 f2 = __half22float2(*(__half2*)&q1.x);
            float2 f3 = __half22float2(*(__half2*)&q1.y);
            float wa = (lane < 16) ? w0 : w1;
            float wb = (lane < 16) ? w2 : w3;
            acc0.x += wa * f0.x; acc0.y += wa * f0.y; acc0.z += wa * f1.x; acc0.w += wa * f1.y;
            acc1.x += wb * f2.x; acc1.y += wb * f2.y; acc1.z += wb * f3.x; acc1.w += wb * f3.y;
        }
    }
    d0 = wsum(d0); d1 = wsum(d1); d2 = wsum(d2); d3 = wsum(d3);
    float inva = (lane < 16) ? (1.f / d0) : (1.f / d1);
    float invb = (lane < 16) ? (1.f / d2) : (1.f / d3);

    float4 r0 = make_float4(elu(acc0.x * inva), elu(acc0.y * inva),
                            elu(acc0.z * inva), elu(acc0.w * inva));
    float4 r1 = make_float4(elu(acc1.x * invb), elu(acc1.y * invb),
                            elu(acc1.z * invb), elu(acc1.w * invb));
    uint2 h0, l0, h1, l1;
    split4(r0, h0, l0);
    split4(r1, h1, l1);
    size_t o0 = ((size_t)gw * 256 + 4 * lane) * 2;
    size_t o1 = ((size_t)gw * 256 + 128 + 4 * lane) * 2;
    *(uint2*)(g_hh + o0) = h0;
    *(uint2*)(g_hl + o0) = l0;
    *(uint2*)(g_hh + o1) = h1;
    *(uint2*)(g_hl + o1) = l1;
}

// ---------------- layer2 attention + ELU + log_softmax ----------------
__global__ void k_gat2(float* __restrict__ out) {
    int gw = (blockIdx.x * blockDim.x + threadIdx.x) >> 5;
    int lane = threadIdx.x & 31;
    if (gw >= NN) return;
    float s2v = __ldg(&g_s2r[gw]);
    int beg = g_off[gw], end = g_off[gw + 1];
    int half = lane >> 4, sl = lane & 15;

    float4 acc = make_float4(0.f, 0.f, 0.f, 0.f);
    float den = 0.f;
    for (int base = beg; base < end; base += 32) {
        int e = base + lane;
        int j = 0; float ex = 0.f;
        if (e < end) {
            j = __ldg(&g_csr[e]);
            ex = __expf(lrelu(s2v + __ldg(&g_s2c[j])));
            den += ex;
        }
        int cnt = min(32, end - base);
        for (int k = 0; k < cnt; k += 2) {
            int kk = k + half;
            int src = (kk < cnt) ? kk : k;
            int   jj = __shfl_sync(0xffffffffu, j,  src);
            float w  = __shfl_sync(0xffffffffu, ex, src);
            if (kk >= cnt) w = 0.f;
            if (sl < 10) {
                float4 v = __ldg((const float4*)&g_Wh2[(size_t)jj * 48 + 4 * sl]);
                acc.x += w * v.x; acc.y += w * v.y; acc.z += w * v.z; acc.w += w * v.w;
            }
        }
    }
    acc.x += __shfl_xor_sync(0xffffffffu, acc.x, 16);
    acc.y += __shfl_xor_sync(0xffffffffu, acc.y, 16);
    acc.z += __shfl_xor_sync(0xffffffffu, acc.z, 16);
    acc.w += __shfl_xor_sync(0xffffffffu, acc.w, 16);
    den = wsum(den);
    float inv = 1.f / den;
    bool valid = (lane < 10);
    float o0 = -1e30f, o1 = -1e30f, o2 = -1e30f, o3 = -1e30f;
    if (valid) {
        o0 = elu(acc.x * inv); o1 = elu(acc.y * inv);
        o2 = elu(acc.z * inv); o3 = elu(acc.w * inv);
    }
    float mm = wmax(fmaxf(fmaxf(o0, o1), fmaxf(o2, o3)));
    float se = 0.f;
    if (valid) se = __expf(o0 - mm) + __expf(o1 - mm) + __expf(o2 - mm) + __expf(o3 - mm);
    se = wsum(se);
    float L = mm + logf(se);
    if (valid)
        *(float4*)&out[(size_t)gw * NCLASS + 4 * lane] = make_float4(o0 - L, o1 - L, o2 - L, o3 - L);
}

// ---------------- launch ----------------
extern "C" void kernel_launch(void* const* d_in, const int* in_sizes, int n_in,
                              void* d_out, int out_size) {
    const float* x    = (const float*)d_in[0];
    const float* W    = (const float*)d_in[1];
    const float* a    = (const float*)d_in[2];
    const float* Wout = (const float*)d_in[3];
    const float* aout = (const float*)d_in[4];
    const int*   row  = (const int*)d_in[5];
    const int*   col  = (const int*)d_in[6];
    int E = in_sizes[5];
    float* out = (float*)d_out;

    static cudaStream_t s2 = nullptr;
    static cudaEvent_t evF = nullptr, evJ = nullptr;
    if (!s2) {
        cudaStreamCreateWithFlags(&s2, cudaStreamNonBlocking);
        cudaEventCreateWithFlags(&evF, cudaEventDisableTiming);
        cudaEventCreateWithFlags(&evJ, cudaEventDisableTiming);
        cudaFuncSetAttribute(k_gemm1, cudaFuncAttributeMaxDynamicSharedMemorySize, S1_BYTES);
        cudaFuncSetAttribute(k_gemm2, cudaFuncAttributeMaxDynamicSharedMemorySize, S2_BYTES);
    }

    // fork CSR chain immediately
    cudaEventRecord(evF, 0);
    cudaStreamWaitEvent(s2, evF, 0);
    k_zero <<<(NN + 255) / 256, 256, 0, s2>>>();
    k_count<<<(E + 255) / 256, 256, 0, s2>>>(row, E);

    k_prep<<<1280, 256>>>(x, W, Wout);
    k_gemm1<<<NTILE, 256, S1_BYTES>>>(a);              // profiled slot

    k_scan1<<<NB1, SB, 0, s2>>>();
    k_scan2<<<1, 256, 0, s2>>>();
    k_scan3<<<NB1, SB, 0, s2>>>(E);
    k_fill <<<(E + 255) / 256, 256, 0, s2>>>(row, col, E);

    cudaEventRecord(evJ, s2);
    cudaStreamWaitEvent(0, evJ, 0);

    k_gat1<<<(NN + 7) / 8, 256>>>();
    k_gemm2<<<NTILE, 256, S2_BYTES>>>(aout);
    k_gat2<<<(NN + 7) / 8, 256>>>(out);
}

// round 9
// speedup vs baseline: 1.4140x; 1.1476x over previous
#include <cuda_runtime.h>
#include <cuda_bf16.h>
#include <cuda_fp16.h>
#include <mma.h>
#include <math.h>
#include <stdint.h>

using namespace nvcuda;

// Problem constants
#define NN      100000
#define EMAX    1700000
#define NCLASS  40
#define SB      512
#define NB1     ((NN + SB - 1) / SB)
#define NTILE   782                    // ceil(NN/128)
#define NPAD    (NTILE * 128)          // 100096

// ---------------- scratch (static device globals) ----------------
__device__ __align__(16) __half g_Wh1h[(size_t)NPAD * 256];  // layer1 Wh fp16 (gather source)
__device__ __align__(16) __half g_Wh2h[(size_t)NPAD * 48];   // layer2 Wh fp16, ld=48
__device__ float g_s1r[NN * 4];
__device__ float g_s1c[NN * 4];
__device__ float g_s2r[NN];
__device__ float g_s2c[NN];
__device__ int   g_deg[NN];
__device__ int   g_cur[NN];
__device__ int   g_off[NN + 1];
__device__ int   g_csr[EMAX];
__device__ int   g_bsum[256];
__device__ int   g_boff[256];
// operands
__device__ __align__(16) __half g_x16[(size_t)NPAD * 128];            // x fp16
__device__ __align__(16) __half g_B1f[128 * 256];                     // B1 fp16 [k][n]
__device__ __align__(16) unsigned char g_hh[(size_t)NPAD * 256 * 2];  // h hi bf16
__device__ __align__(16) unsigned char g_hl[(size_t)NPAD * 256 * 2];  // h lo bf16
__device__ __align__(16) unsigned char g_B2h[256 * 48 * 2];           // B2 hi bf16 [k][n] ld 48
__device__ __align__(16) unsigned char g_B2l[256 * 48 * 2];

// ---------------- helpers ----------------
__device__ __forceinline__ uint32_t smem_u32(const void* p) {
    uint32_t a;
    asm("{ .reg .u64 t; cvta.to.shared.u64 t, %1; cvt.u32.u64 %0, t; }" : "=r"(a) : "l"(p));
    return a;
}
__device__ __forceinline__ void cpa16(uint32_t dst, const void* src) {
    asm volatile("cp.async.cg.shared.global [%0], [%1], 16;" :: "r"(dst), "l"(src));
}
#define CP_COMMIT() asm volatile("cp.async.commit_group;" ::: "memory")
#define CP_WAIT1()  asm volatile("cp.async.wait_group 1;" ::: "memory")
#define CP_WAIT0()  asm volatile("cp.async.wait_group 0;" ::: "memory")

__device__ __forceinline__ float wmax(float v) {
    #pragma unroll
    for (int o = 16; o; o >>= 1) v = fmaxf(v, __shfl_xor_sync(0xffffffffu, v, o));
    return v;
}
__device__ __forceinline__ float wsum(float v) {
    #pragma unroll
    for (int o = 16; o; o >>= 1) v += __shfl_xor_sync(0xffffffffu, v, o);
    return v;
}
__device__ __forceinline__ float lrelu(float v) { return v > 0.f ? v : 0.1f * v; }
__device__ __forceinline__ float elu(float v)   { return v > 0.f ? v : expm1f(v); }

__device__ __forceinline__ void split4(float4 v, uint2& hi, uint2& lo) {
    __nv_bfloat16 h0 = __float2bfloat16_rn(v.x), h1 = __float2bfloat16_rn(v.y),
                  h2 = __float2bfloat16_rn(v.z), h3 = __float2bfloat16_rn(v.w);
    hi.x = ((uint32_t)__bfloat16_as_ushort(h1) << 16) | __bfloat16_as_ushort(h0);
    hi.y = ((uint32_t)__bfloat16_as_ushort(h3) << 16) | __bfloat16_as_ushort(h2);
    __nv_bfloat162 l01 = __floats2bfloat162_rn(v.x - __bfloat162float(h0), v.y - __bfloat162float(h1));
    __nv_bfloat162 l23 = __floats2bfloat162_rn(v.z - __bfloat162float(h2), v.w - __bfloat162float(h3));
    lo.x = *(uint32_t*)&l01;
    lo.y = *(uint32_t*)&l23;
}

// ---------------- prep: x -> fp16, B1 -> fp16, B2 -> bf16 hi/lo, zero h pad ----------------
#define XIT 3200000   // NN*128/4 float4 items
__global__ void k_prep(const float* __restrict__ x, const float* __restrict__ W,
                       const float* __restrict__ Wout) {
    int stride = gridDim.x * blockDim.x;
    for (int i = blockIdx.x * blockDim.x + threadIdx.x; i < XIT + 32768 + 12288 + 6144; i += stride) {
        if (i < XIT) {
            int r = i >> 5, kq = (i & 31) * 4;
            float4 v = __ldg((const float4*)&x[(size_t)r * 128 + kq]);
            __half2 p0 = __floats2half2_rn(v.x, v.y);
            __half2 p1 = __floats2half2_rn(v.z, v.w);
            uint2 o = make_uint2(*(uint32_t*)&p0, *(uint32_t*)&p1);
            *(uint2*)&g_x16[(size_t)r * 128 + kq] = o;
        } else if (i < XIT + 32768) {
            int i2 = i - XIT;
            int k = i2 >> 8, n = i2 & 255;
            float v = W[(n >> 6) * 8192 + k * 64 + (n & 63)];
            g_B1f[i2] = __float2half_rn(v);
        } else if (i < XIT + 32768 + 12288) {
            int j = i - XIT - 32768;
            int k = j / 48, n = j - k * 48;
            float v = (n < NCLASS) ? Wout[k * NCLASS + n] : 0.f;
            __nv_bfloat16 h = __float2bfloat16_rn(v);
            __nv_bfloat16 l = __float2bfloat16_rn(v - __bfloat162float(h));
            *(__nv_bfloat16*)(g_B2h + (size_t)j * 2) = h;
            *(__nv_bfloat16*)(g_B2l + (size_t)j * 2) = l;
        } else {
            int j = i - XIT - 45056;
            uint4 z = make_uint4(0, 0, 0, 0);
            if (j < 3072) *(uint4*)(g_hh + (size_t)NN * 512 + (size_t)j * 16) = z;
            else          *(uint4*)(g_hl + (size_t)NN * 512 + (size_t)(j - 3072) * 16) = z;
        }
    }
}

// ---------------- CSR build ----------------
__global__ void k_zero() {
    int i = blockIdx.x * blockDim.x + threadIdx.x;
    if (i < NN) { g_deg[i] = 0; g_cur[i] = 0; }
}
__global__ void k_count(const int* __restrict__ row, int E) {
    int e = blockIdx.x * blockDim.x + threadIdx.x;
    if (e < E) atomicAdd(&g_deg[__ldg(&row[e])], 1);
}
__global__ void k_scan1() {
    __shared__ int s[SB];
    int tid = threadIdx.x, g = blockIdx.x * SB + tid;
    int v = (g < NN) ? g_deg[g] : 0;
    s[tid] = v; __syncthreads();
    for (int o = 1; o < SB; o <<= 1) {
        int t = (tid >= o) ? s[tid - o] : 0;
        __syncthreads(); s[tid] += t; __syncthreads();
    }
    if (g < NN) g_off[g] = s[tid] - v;
    if (tid == SB - 1) g_bsum[blockIdx.x] = s[tid];
}
__global__ void k_scan2() {
    __shared__ int s[256];
    int tid = threadIdx.x;
    int v = (tid < NB1) ? g_bsum[tid] : 0;
    s[tid] = v; __syncthreads();
    for (int o = 1; o < 256; o <<= 1) {
        int t = (tid >= o) ? s[tid - o] : 0;
        __syncthreads(); s[tid] += t; __syncthreads();
    }
    g_boff[tid] = s[tid] - v;
}
__global__ void k_scan3(int E) {
    int tid = threadIdx.x, g = blockIdx.x * SB + tid;
    if (g < NN) g_off[g] += g_boff[blockIdx.x];
    if (g == 0) g_off[NN] = E;
}
__global__ void k_fill(const int* __restrict__ row, const int* __restrict__ col, int E) {
    int e = blockIdx.x * blockDim.x + threadIdx.x;
    if (e >= E) return;
    int r = __ldg(&row[e]);
    int p = g_off[r] + atomicAdd(&g_cur[r], 1);
    g_csr[p] = __ldg(&col[e]);
}

// ---------------- GEMM1: Wh1 = x @ B1 [128x256, K=128, fp16 single-pass, fused s1] ----------------
#define T1_A 0
#define T1_B 18432
#define T1_STAGE 52224
// smem must also hold the fp32 epilogue tile: 128 * 264 * 4 = 135168 > 2*T1_STAGE
#define T1_BYTES 135168

__global__ __launch_bounds__(256) void k_gemm1(const float* __restrict__ a) {
    extern __shared__ __align__(16) unsigned char smem[];
    uint32_t sbase = smem_u32(smem);
    int tid = threadIdx.x;
    int m0 = blockIdx.x * 128;

    // issue cp.async for both 64-wide k-chunks
    #pragma unroll
    for (int c = 0; c < 2; c++) {
        uint32_t st = sbase + c * T1_STAGE;
        #pragma unroll
        for (int t = 0; t < 4; t++) {           // A: 1024 chunks
            int idx = tid + t * 256;
            int r = idx >> 3, c8 = idx & 7;
            size_t so = ((size_t)(m0 + r) * 128 + c * 64 + c8 * 8) * 2;
            cpa16(st + T1_A + (uint32_t)(r * 72 + c8 * 8) * 2, (const unsigned char*)g_x16 + so);
        }
        #pragma unroll
        for (int t = 0; t < 8; t++) {           // B: 2048 chunks
            int idx = tid + t * 256;
            int kr = idx >> 5, c16 = idx & 31;
            size_t so = ((size_t)(c * 64 + kr) * 256 + c16 * 8) * 2;
            cpa16(st + T1_B + (uint32_t)(kr * 264 + c16 * 8) * 2, (const unsigned char*)g_B1f + so);
        }
        CP_COMMIT();
    }

    int wid = tid >> 5, wm = wid & 1, wn = wid >> 1;  // 2M x 4N warps, tile 64x64

    wmma::fragment<wmma::accumulator, 16, 16, 16, float> acc[4][4];
    #pragma unroll
    for (int i = 0; i < 4; i++)
        #pragma unroll
        for (int j = 0; j < 4; j++) wmma::fill_fragment(acc[i][j], 0.f);

    CP_WAIT1();
    __syncthreads();

    #pragma unroll
    for (int c = 0; c < 2; c++) {
        const unsigned char* st = smem + c * T1_STAGE;
        const __half* A_ = (const __half*)(st + T1_A);
        const __half* B_ = (const __half*)(st + T1_B);
        #pragma unroll
        for (int k8 = 0; k8 < 4; k8++) {
            wmma::fragment<wmma::matrix_a, 16, 16, 16, __half, wmma::row_major> af[4];
            wmma::fragment<wmma::matrix_b, 16, 16, 16, __half, wmma::row_major> bfr[4];
            #pragma unroll
            for (int i = 0; i < 4; i++)
                wmma::load_matrix_sync(af[i], A_ + (wm * 64 + i * 16) * 72 + k8 * 16, 72);
            #pragma unroll
            for (int j = 0; j < 4; j++)
                wmma::load_matrix_sync(bfr[j], B_ + (k8 * 16) * 264 + wn * 64 + j * 16, 264);
            #pragma unroll
            for (int i = 0; i < 4; i++)
                #pragma unroll
                for (int j = 0; j < 4; j++)
                    wmma::mma_sync(acc[i][j], af[i], bfr[j], acc[i][j]);
        }
        if (c == 0) { CP_WAIT0(); __syncthreads(); }
    }

    // epilogue: stage fp32 tile in smem (ld 264), write fp16 Wh1, fused s1
    __syncthreads();
    float* tile = (float*)smem;
    #pragma unroll
    for (int i = 0; i < 4; i++)
        #pragma unroll
        for (int j = 0; j < 4; j++)
            wmma::store_matrix_sync(&tile[(wm * 64 + i * 16) * 264 + wn * 64 + j * 16],
                                    acc[i][j], 264, wmma::mem_row_major);
    __syncthreads();

    #pragma unroll
    for (int t = 0; t < 32; t++) {
        int idx = tid + t * 256;
        int r = idx >> 6, c4 = idx & 63;
        float4 v = *(const float4*)&tile[r * 264 + c4 * 4];
        __half2 p0 = __floats2half2_rn(v.x, v.y);
        __half2 p1 = __floats2half2_rn(v.z, v.w);
        uint2 o = make_uint2(*(uint32_t*)&p0, *(uint32_t*)&p1);
        *(uint2*)&g_Wh1h[(size_t)(m0 + r) * 256 + c4 * 4] = o;
    }
    {
        int h = tid & 3;
        #pragma unroll
        for (int rr = 0; rr < 2; rr++) {
            int row = (tid >> 2) + rr * 64;
            const float* rp = &tile[row * 264 + h * 64];
            float sr = 0.f, sc = 0.f;
            #pragma unroll
            for (int jx = 0; jx < 64; jx++) {
                int j = (h * 16 + jx) & 63;
                float v = rp[j];
                sr += v * __ldg(&a[h * 128 + j]);
                sc += v * __ldg(&a[h * 128 + 64 + j]);
            }
            int gr = m0 + row;
            if (gr < NN) {
                g_s1r[gr * 4 + h] = sr;
                g_s1c[gr * 4 + h] = sc;
            }
        }
    }
}

// ---------------- GEMM2: Wh2 = h @ B2 [128x48, K=256, bf16 3-pass, fused s2] ----------------
#define S2_AH 0
#define S2_AL 34816
#define S2_BH 69632
#define S2_BL 83968
#define S2_STAGE 98304
#define S2_BYTES (2 * S2_STAGE)

__global__ __launch_bounds__(256) void k_gemm2(const float* __restrict__ aout) {
    extern __shared__ __align__(16) unsigned char smem[];
    uint32_t sbase = smem_u32(smem);
    int tid = threadIdx.x;
    int m0 = blockIdx.x * 128;

    #pragma unroll
    for (int c = 0; c < 2; c++) {
        uint32_t st = sbase + c * S2_STAGE;
        #pragma unroll
        for (int t = 0; t < 8; t++) {
            int idx = tid + t * 256;
            int r = idx >> 4, c16 = idx & 15;
            size_t so = ((size_t)(m0 + r) * 256 + c * 128 + c16 * 8) * 2;
            uint32_t doff = (uint32_t)(r * 136 + c16 * 8) * 2;
            cpa16(st + S2_AH + doff, g_hh + so);
            cpa16(st + S2_AL + doff, g_hl + so);
        }
        #pragma unroll
        for (int t = 0; t < 3; t++) {
            int idx = tid + t * 256;
            int kr = idx / 6, c6 = idx - kr * 6;
            size_t so = ((size_t)(c * 128 + kr) * 48 + c6 * 8) * 2;
            uint32_t doff = (uint32_t)(kr * 56 + c6 * 8) * 2;
            cpa16(st + S2_BH + doff, g_B2h + so);
            cpa16(st + S2_BL + doff, g_B2l + so);
        }
        CP_COMMIT();
    }

    int wid = tid >> 5;

    wmma::fragment<wmma::accumulator, 16, 16, 16, float> acc[3];
    #pragma unroll
    for (int j = 0; j < 3; j++) wmma::fill_fragment(acc[j], 0.f);

    CP_WAIT1();
    __syncthreads();

    #pragma unroll
    for (int c = 0; c < 2; c++) {
        const unsigned char* st = smem + c * S2_STAGE;
        #pragma unroll
        for (int pass = 0; pass < 3; pass++) {
            const __nv_bfloat16* A_ = (const __nv_bfloat16*)(st + (pass == 2 ? S2_AL : S2_AH));
            const __nv_bfloat16* B_ = (const __nv_bfloat16*)(st + (pass == 1 ? S2_BL : S2_BH));
            #pragma unroll
            for (int k16 = 0; k16 < 8; k16++) {
                wmma::fragment<wmma::matrix_a, 16, 16, 16, __nv_bfloat16, wmma::row_major> af;
                wmma::fragment<wmma::matrix_b, 16, 16, 16, __nv_bfloat16, wmma::row_major> bfr[3];
                wmma::load_matrix_sync(af, A_ + (wid * 16) * 136 + k16 * 16, 136);
                #pragma unroll
                for (int j = 0; j < 3; j++)
                    wmma::load_matrix_sync(bfr[j], B_ + (k16 * 16) * 56 + j * 16, 56);
                #pragma unroll
                for (int j = 0; j < 3; j++)
                    wmma::mma_sync(acc[j], af, bfr[j], acc[j]);
            }
        }
        if (c == 0) { CP_WAIT0(); __syncthreads(); }
    }

    __syncthreads();
    float* tile = (float*)smem;
    #pragma unroll
    for (int j = 0; j < 3; j++)
        wmma::store_matrix_sync(&tile[(wid * 16) * 56 + j * 16], acc[j], 56, wmma::mem_row_major);
    __syncthreads();

    #pragma unroll
    for (int t = 0; t < 6; t++) {               // fp16 Wh2 store
        int idx = tid + t * 256;
        int r = idx / 12, c4 = idx - r * 12;
        float4 v = *(const float4*)&tile[r * 56 + c4 * 4];
        __half2 p0 = __floats2half2_rn(v.x, v.y);
        __half2 p1 = __floats2half2_rn(v.z, v.w);
        uint2 o = make_uint2(*(uint32_t*)&p0, *(uint32_t*)&p1);
        *(uint2*)&g_Wh2h[(size_t)(m0 + r) * 48 + c4 * 4] = o;
    }
    if (tid < 128) {
        int row = tid;
        const float* rp = &tile[row * 56];
        float sr = 0.f, sc = 0.f;
        #pragma unroll
        for (int j = 0; j < 40; j++) {
            float v = rp[j];
            sr += v * __ldg(&aout[j]);
            sc += v * __ldg(&aout[40 + j]);
        }
        int gr = m0 + row;
        if (gr < NN) { g_s2r[gr] = sr; g_s2c[gr] = sc; }
    }
}

// ---------------- layer1 aggregation (warp per node, fp16 gathers); emits h as bf16 hi/lo ----------------
__global__ void k_gat1() {
    int gw = (blockIdx.x * blockDim.x + threadIdx.x) >> 5;
    int lane = threadIdx.x & 31;
    if (gw >= NN) return;
    const float4 sr = *(const float4*)&g_s1r[gw * 4];
    int beg = g_off[gw], end = g_off[gw + 1];

    float4 acc0 = make_float4(0.f, 0.f, 0.f, 0.f);
    float4 acc1 = make_float4(0.f, 0.f, 0.f, 0.f);
    float d0 = 0.f, d1 = 0.f, d2 = 0.f, d3 = 0.f;

    for (int base = beg; base < end; base += 32) {
        int e = base + lane;
        int j = 0; float ex0 = 0.f, ex1 = 0.f, ex2 = 0.f, ex3 = 0.f;
        if (e < end) {
            j = __ldg(&g_csr[e]);
            float4 s = __ldg((const float4*)&g_s1c[j * 4]);
            ex0 = __expf(lrelu(sr.x + s.x));
            ex1 = __expf(lrelu(sr.y + s.y));
            ex2 = __expf(lrelu(sr.z + s.z));
            ex3 = __expf(lrelu(sr.w + s.w));
            d0 += ex0; d1 += ex1; d2 += ex2; d3 += ex3;
        }
        int cnt = min(32, end - base);
        for (int k = 0; k < cnt; k++) {
            int   jj = __shfl_sync(0xffffffffu, j,   k);
            float w0 = __shfl_sync(0xffffffffu, ex0, k);
            float w1 = __shfl_sync(0xffffffffu, ex1, k);
            float w2 = __shfl_sync(0xffffffffu, ex2, k);
            float w3 = __shfl_sync(0xffffffffu, ex3, k);
            const __half* wp = &g_Wh1h[(size_t)jj * 256];
            uint2 q0 = __ldg((const uint2*)(wp + 4 * lane));
            uint2 q1 = __ldg((const uint2*)(wp + 128 + 4 * lane));
            float2 f0 = __half22float2(*(__half2*)&q0.x);
            float2 f1 = __half22float2(*(__half2*)&q0.y);
            float2 f2 = __half22float2(*(__half2*)&q1.x);
            float2 f3 = __half22float2(*(__half2*)&q1.y);
            float wa = (lane < 16) ? w0 : w1;
            float wb = (lane < 16) ? w2 : w3;
            acc0.x += wa * f0.x; acc0.y += wa * f0.y; acc0.z += wa * f1.x; acc0.w += wa * f1.y;
            acc1.x += wb * f2.x; acc1.y += wb * f2.y; acc1.z += wb * f3.x; acc1.w += wb * f3.y;
        }
    }
    d0 = wsum(d0); d1 = wsum(d1); d2 = wsum(d2); d3 = wsum(d3);
    float inva = (lane < 16) ? (1.f / d0) : (1.f / d1);
    float invb = (lane < 16) ? (1.f / d2) : (1.f / d3);

    float4 r0 = make_float4(elu(acc0.x * inva), elu(acc0.y * inva),
                            elu(acc0.z * inva), elu(acc0.w * inva));
    float4 r1 = make_float4(elu(acc1.x * invb), elu(acc1.y * invb),
                            elu(acc1.z * invb), elu(acc1.w * invb));
    uint2 h0, l0, h1, l1;
    split4(r0, h0, l0);
    split4(r1, h1, l1);
    size_t o0 = ((size_t)gw * 256 + 4 * lane) * 2;
    size_t o1 = ((size_t)gw * 256 + 128 + 4 * lane) * 2;
    *(uint2*)(g_hh + o0) = h0;
    *(uint2*)(g_hl + o0) = l0;
    *(uint2*)(g_hh + o1) = h1;
    *(uint2*)(g_hl + o1) = l1;
}

// ---------------- layer2 attention + ELU + log_softmax (fp16 gathers) ----------------
__global__ void k_gat2(float* __restrict__ out) {
    int gw = (blockIdx.x * blockDim.x + threadIdx.x) >> 5;
    int lane = threadIdx.x & 31;
    if (gw >= NN) return;
    float s2v = __ldg(&g_s2r[gw]);
    int beg = g_off[gw], end = g_off[gw + 1];
    int half = lane >> 4, sl = lane & 15;

    float4 acc = make_float4(0.f, 0.f, 0.f, 0.f);
    float den = 0.f;
    for (int base = beg; base < end; base += 32) {
        int e = base + lane;
        int j = 0; float ex = 0.f;
        if (e < end) {
            j = __ldg(&g_csr[e]);
            ex = __expf(lrelu(s2v + __ldg(&g_s2c[j])));
            den += ex;
        }
        int cnt = min(32, end - base);
        for (int k = 0; k < cnt; k += 2) {
            int kk = k + half;
            int src = (kk < cnt) ? kk : k;
            int   jj = __shfl_sync(0xffffffffu, j,  src);
            float w  = __shfl_sync(0xffffffffu, ex, src);
            if (kk >= cnt) w = 0.f;
            if (sl < 10) {
                uint2 q = __ldg((const uint2*)&g_Wh2h[(size_t)jj * 48 + 4 * sl]);
                float2 f0 = __half22float2(*(__half2*)&q.x);
                float2 f1 = __half22float2(*(__half2*)&q.y);
                acc.x += w * f0.x; acc.y += w * f0.y; acc.z += w * f1.x; acc.w += w * f1.y;
            }
        }
    }
    acc.x += __shfl_xor_sync(0xffffffffu, acc.x, 16);
    acc.y += __shfl_xor_sync(0xffffffffu, acc.y, 16);
    acc.z += __shfl_xor_sync(0xffffffffu, acc.z, 16);
    acc.w += __shfl_xor_sync(0xffffffffu, acc.w, 16);
    den = wsum(den);
    float inv = 1.f / den;
    bool valid = (lane < 10);
    float o0 = -1e30f, o1 = -1e30f, o2 = -1e30f, o3 = -1e30f;
    if (valid) {
        o0 = elu(acc.x * inv); o1 = elu(acc.y * inv);
        o2 = elu(acc.z * inv); o3 = elu(acc.w * inv);
    }
    float mm = wmax(fmaxf(fmaxf(o0, o1), fmaxf(o2, o3)));
    float se = 0.f;
    if (valid) se = __expf(o0 - mm) + __expf(o1 - mm) + __expf(o2 - mm) + __expf(o3 - mm);
    se = wsum(se);
    float L = mm + logf(se);
    if (valid)
        *(float4*)&out[(size_t)gw * NCLASS + 4 * lane] = make_float4(o0 - L, o1 - L, o2 - L, o3 - L);
}

// ---------------- launch ----------------
extern "C" void kernel_launch(void* const* d_in, const int* in_sizes, int n_in,
                              void* d_out, int out_size) {
    const float* x    = (const float*)d_in[0];
    const float* W    = (const float*)d_in[1];
    const float* a    = (const float*)d_in[2];
    const float* Wout = (const float*)d_in[3];
    const float* aout = (const float*)d_in[4];
    const int*   row  = (const int*)d_in[5];
    const int*   col  = (const int*)d_in[6];
    int E = in_sizes[5];
    float* out = (float*)d_out;

    static cudaStream_t s2 = nullptr;
    static cudaEvent_t evF = nullptr, evJ = nullptr;
    if (!s2) {
        cudaStreamCreateWithFlags(&s2, cudaStreamNonBlocking);
        cudaEventCreateWithFlags(&evF, cudaEventDisableTiming);
        cudaEventCreateWithFlags(&evJ, cudaEventDisableTiming);
        cudaFuncSetAttribute(k_gemm1, cudaFuncAttributeMaxDynamicSharedMemorySize, T1_BYTES);
        cudaFuncSetAttribute(k_gemm2, cudaFuncAttributeMaxDynamicSharedMemorySize, S2_BYTES);
    }

    // fork CSR chain immediately
    cudaEventRecord(evF, 0);
    cudaStreamWaitEvent(s2, evF, 0);
    k_zero <<<(NN + 255) / 256, 256, 0, s2>>>();
    k_count<<<(E + 255) / 256, 256, 0, s2>>>(row, E);

    k_prep<<<1280, 256>>>(x, W, Wout);
    k_gemm1<<<NTILE, 256, T1_BYTES>>>(a);              // profiled slot

    k_scan1<<<NB1, SB, 0, s2>>>();
    k_scan2<<<1, 256, 0, s2>>>();
    k_scan3<<<NB1, SB, 0, s2>>>(E);
    k_fill <<<(E + 255) / 256, 256, 0, s2>>>(row, col, E);

    cudaEventRecord(evJ, s2);
    cudaStreamWaitEvent(0, evJ, 0);

    k_gat1<<<(NN + 7) / 8, 256>>>();
    k_gemm2<<<NTILE, 256, S2_BYTES>>>(aout);
    k_gat2<<<(NN + 7) / 8, 256>>>(out);
}

// round 10
// speedup vs baseline: 1.5736x; 1.1129x over previous
#include <cuda_runtime.h>
#include <cuda_bf16.h>
#include <cuda_fp16.h>
#include <mma.h>
#include <math.h>
#include <stdint.h>

using namespace nvcuda;

// Problem constants
#define NN      100000
#define EMAX    1700000
#define NCLASS  40
#define SB      512
#define NB1     ((NN + SB - 1) / SB)
#define NTILE   782                    // ceil(NN/128)
#define NPAD    (NTILE * 128)          // 100096

// ---------------- scratch (static device globals) ----------------
__device__ __align__(16) __half g_Wh1h[(size_t)NPAD * 256];  // layer1 Wh fp16 (gather source)
__device__ __align__(16) __half g_Wh2h[(size_t)NPAD * 48];   // layer2 Wh fp16, ld=48
__device__ __align__(16) __half g_h16[(size_t)NPAD * 256];   // layer1 output fp16 (gemm2 A)
__device__ float g_s1r[NN * 4];
__device__ float g_s1c[NN * 4];
__device__ float g_s2r[NN];
__device__ float g_s2c[NN];
__device__ int   g_deg[NN];
__device__ int   g_cur[NN];
__device__ int   g_off[NN + 1];
__device__ int   g_csr[EMAX];
__device__ int   g_bsum[256];
__device__ int   g_boff[256];
// operands
__device__ __align__(16) __half g_x16[(size_t)NPAD * 128];   // x fp16
__device__ __align__(16) __half g_B1f[128 * 256];            // B1 fp16 [k][n] ld 256
__device__ __align__(16) __half g_B2f[256 * 48];             // B2 fp16 [k][n] ld 48 (n>=40 zero)

// ---------------- helpers ----------------
__device__ __forceinline__ uint32_t smem_u32(const void* p) {
    uint32_t a;
    asm("{ .reg .u64 t; cvta.to.shared.u64 t, %1; cvt.u32.u64 %0, t; }" : "=r"(a) : "l"(p));
    return a;
}
__device__ __forceinline__ void cpa16(uint32_t dst, const void* src) {
    asm volatile("cp.async.cg.shared.global [%0], [%1], 16;" :: "r"(dst), "l"(src));
}
#define CP_COMMIT() asm volatile("cp.async.commit_group;" ::: "memory")
#define CP_WAIT1()  asm volatile("cp.async.wait_group 1;" ::: "memory")
#define CP_WAIT0()  asm volatile("cp.async.wait_group 0;" ::: "memory")

__device__ __forceinline__ float wmax(float v) {
    #pragma unroll
    for (int o = 16; o; o >>= 1) v = fmaxf(v, __shfl_xor_sync(0xffffffffu, v, o));
    return v;
}
__device__ __forceinline__ float wsum(float v) {
    #pragma unroll
    for (int o = 16; o; o >>= 1) v += __shfl_xor_sync(0xffffffffu, v, o);
    return v;
}
__device__ __forceinline__ float lrelu(float v) { return v > 0.f ? v : 0.1f * v; }
__device__ __forceinline__ float elu(float v)   { return v > 0.f ? v : expm1f(v); }

// ---------------- prep: x/B1/B2 -> fp16, zero h16 pad rows ----------------
#define XIT 3200000   // NN*128/4 float4 items
#define PB1 32768
#define PB2 12288
#define PZH 3072      // pad rows of g_h16: 96*256 halves = 3072 uint4
__global__ void k_prep(const float* __restrict__ x, const float* __restrict__ W,
                       const float* __restrict__ Wout) {
    int stride = gridDim.x * blockDim.x;
    for (int i = blockIdx.x * blockDim.x + threadIdx.x; i < XIT + PB1 + PB2 + PZH; i += stride) {
        if (i < XIT) {
            int r = i >> 5, kq = (i & 31) * 4;
            float4 v = __ldg((const float4*)&x[(size_t)r * 128 + kq]);
            __half2 p0 = __floats2half2_rn(v.x, v.y);
            __half2 p1 = __floats2half2_rn(v.z, v.w);
            uint2 o = make_uint2(*(uint32_t*)&p0, *(uint32_t*)&p1);
            *(uint2*)&g_x16[(size_t)r * 128 + kq] = o;
        } else if (i < XIT + PB1) {
            int i2 = i - XIT;
            int k = i2 >> 8, n = i2 & 255;
            float v = W[(n >> 6) * 8192 + k * 64 + (n & 63)];
            g_B1f[i2] = __float2half_rn(v);
        } else if (i < XIT + PB1 + PB2) {
            int j = i - XIT - PB1;
            int k = j / 48, n = j - k * 48;
            float v = (n < NCLASS) ? Wout[k * NCLASS + n] : 0.f;
            g_B2f[j] = __float2half_rn(v);
        } else {
            int j = i - XIT - PB1 - PB2;
            *(uint4*)((unsigned char*)g_h16 + (size_t)NN * 512 + (size_t)j * 16) =
                make_uint4(0, 0, 0, 0);
        }
    }
}

// ---------------- CSR build ----------------
__global__ void k_zero() {
    int i = blockIdx.x * blockDim.x + threadIdx.x;
    if (i < NN) { g_deg[i] = 0; g_cur[i] = 0; }
}
__global__ void k_count(const int* __restrict__ row, int E) {
    int e = blockIdx.x * blockDim.x + threadIdx.x;
    if (e < E) atomicAdd(&g_deg[__ldg(&row[e])], 1);
}
__global__ void k_scan1() {
    __shared__ int s[SB];
    int tid = threadIdx.x, g = blockIdx.x * SB + tid;
    int v = (g < NN) ? g_deg[g] : 0;
    s[tid] = v; __syncthreads();
    for (int o = 1; o < SB; o <<= 1) {
        int t = (tid >= o) ? s[tid - o] : 0;
        __syncthreads(); s[tid] += t; __syncthreads();
    }
    if (g < NN) g_off[g] = s[tid] - v;
    if (tid == SB - 1) g_bsum[blockIdx.x] = s[tid];
}
__global__ void k_scan2() {
    __shared__ int s[256];
    int tid = threadIdx.x;
    int v = (tid < NB1) ? g_bsum[tid] : 0;
    s[tid] = v; __syncthreads();
    for (int o = 1; o < 256; o <<= 1) {
        int t = (tid >= o) ? s[tid - o] : 0;
        __syncthreads(); s[tid] += t; __syncthreads();
    }
    g_boff[tid] = s[tid] - v;
}
__global__ void k_scan3(int E) {
    int tid = threadIdx.x, g = blockIdx.x * SB + tid;
    if (g < NN) g_off[g] += g_boff[blockIdx.x];
    if (g == 0) g_off[NN] = E;
}
__global__ void k_fill(const int* __restrict__ row, const int* __restrict__ col, int E) {
    int e = blockIdx.x * blockDim.x + threadIdx.x;
    if (e >= E) return;
    int r = __ldg(&row[e]);
    int p = g_off[r] + atomicAdd(&g_cur[r], 1);
    g_csr[p] = __ldg(&col[e]);
}

// ---------------- GEMM1: Wh1 = x @ B1 [128x256, K=128, fp16 single-pass, fused s1] ----------------
#define T1_A 0
#define T1_B 18432
#define T1_STAGE 52224
// smem must also hold the fp32 epilogue tile: 128 * 264 * 4 = 135168 > 2*T1_STAGE
#define T1_BYTES 135168

__global__ __launch_bounds__(256) void k_gemm1(const float* __restrict__ a) {
    extern __shared__ __align__(16) unsigned char smem[];
    uint32_t sbase = smem_u32(smem);
    int tid = threadIdx.x;
    int m0 = blockIdx.x * 128;

    #pragma unroll
    for (int c = 0; c < 2; c++) {
        uint32_t st = sbase + c * T1_STAGE;
        #pragma unroll
        for (int t = 0; t < 4; t++) {           // A: 1024 chunks
            int idx = tid + t * 256;
            int r = idx >> 3, c8 = idx & 7;
            size_t so = ((size_t)(m0 + r) * 128 + c * 64 + c8 * 8) * 2;
            cpa16(st + T1_A + (uint32_t)(r * 72 + c8 * 8) * 2, (const unsigned char*)g_x16 + so);
        }
        #pragma unroll
        for (int t = 0; t < 8; t++) {           // B: 2048 chunks
            int idx = tid + t * 256;
            int kr = idx >> 5, c16 = idx & 31;
            size_t so = ((size_t)(c * 64 + kr) * 256 + c16 * 8) * 2;
            cpa16(st + T1_B + (uint32_t)(kr * 264 + c16 * 8) * 2, (const unsigned char*)g_B1f + so);
        }
        CP_COMMIT();
    }

    int wid = tid >> 5, wm = wid & 1, wn = wid >> 1;  // 2M x 4N warps, tile 64x64

    wmma::fragment<wmma::accumulator, 16, 16, 16, float> acc[4][4];
    #pragma unroll
    for (int i = 0; i < 4; i++)
        #pragma unroll
        for (int j = 0; j < 4; j++) wmma::fill_fragment(acc[i][j], 0.f);

    CP_WAIT1();
    __syncthreads();

    #pragma unroll
    for (int c = 0; c < 2; c++) {
        const unsigned char* st = smem + c * T1_STAGE;
        const __half* A_ = (const __half*)(st + T1_A);
        const __half* B_ = (const __half*)(st + T1_B);
        #pragma unroll
        for (int k8 = 0; k8 < 4; k8++) {
            wmma::fragment<wmma::matrix_a, 16, 16, 16, __half, wmma::row_major> af[4];
            wmma::fragment<wmma::matrix_b, 16, 16, 16, __half, wmma::row_major> bfr[4];
            #pragma unroll
            for (int i = 0; i < 4; i++)
                wmma::load_matrix_sync(af[i], A_ + (wm * 64 + i * 16) * 72 + k8 * 16, 72);
            #pragma unroll
            for (int j = 0; j < 4; j++)
                wmma::load_matrix_sync(bfr[j], B_ + (k8 * 16) * 264 + wn * 64 + j * 16, 264);
            #pragma unroll
            for (int i = 0; i < 4; i++)
                #pragma unroll
                for (int j = 0; j < 4; j++)
                    wmma::mma_sync(acc[i][j], af[i], bfr[j], acc[i][j]);
        }
        if (c == 0) { CP_WAIT0(); __syncthreads(); }
    }

    // epilogue: stage fp32 tile in smem (ld 264), write fp16 Wh1, fused s1
    __syncthreads();
    float* tile = (float*)smem;
    #pragma unroll
    for (int i = 0; i < 4; i++)
        #pragma unroll
        for (int j = 0; j < 4; j++)
            wmma::store_matrix_sync(&tile[(wm * 64 + i * 16) * 264 + wn * 64 + j * 16],
                                    acc[i][j], 264, wmma::mem_row_major);
    __syncthreads();

    #pragma unroll
    for (int t = 0; t < 32; t++) {
        int idx = tid + t * 256;
        int r = idx >> 6, c4 = idx & 63;
        float4 v = *(const float4*)&tile[r * 264 + c4 * 4];
        __half2 p0 = __floats2half2_rn(v.x, v.y);
        __half2 p1 = __floats2half2_rn(v.z, v.w);
        uint2 o = make_uint2(*(uint32_t*)&p0, *(uint32_t*)&p1);
        *(uint2*)&g_Wh1h[(size_t)(m0 + r) * 256 + c4 * 4] = o;
    }
    // fused s1: float4-vectorized dot (16 iters per row-head)
    {
        int h = tid & 3;
        #pragma unroll
        for (int rr = 0; rr < 2; rr++) {
            int row = (tid >> 2) + rr * 64;
            const float* rp = &tile[row * 264 + h * 64];
            float sr = 0.f, sc = 0.f;
            #pragma unroll
            for (int q = 0; q < 16; q++) {
                float4 v  = *(const float4*)&rp[q * 4];
                float4 ar = __ldg((const float4*)&a[h * 128 + q * 4]);
                float4 ac = __ldg((const float4*)&a[h * 128 + 64 + q * 4]);
                sr += v.x * ar.x + v.y * ar.y + v.z * ar.z + v.w * ar.w;
                sc += v.x * ac.x + v.y * ac.y + v.z * ac.z + v.w * ac.w;
            }
            int gr = m0 + row;
            if (gr < NN) {
                g_s1r[gr * 4 + h] = sr;
                g_s1c[gr * 4 + h] = sc;
            }
        }
    }
}

// ---------------- GEMM2: Wh2 = h16 @ B2 [128x48, K=256, fp16 single-pass, fused s2] ----------------
#define T2_A 0
#define T2_B 34816
#define T2_STAGE 49152
#define T2_BYTES (2 * T2_STAGE)

__global__ __launch_bounds__(256) void k_gemm2(const float* __restrict__ aout) {
    extern __shared__ __align__(16) unsigned char smem[];
    uint32_t sbase = smem_u32(smem);
    int tid = threadIdx.x;
    int m0 = blockIdx.x * 128;

    #pragma unroll
    for (int c = 0; c < 2; c++) {
        uint32_t st = sbase + c * T2_STAGE;
        #pragma unroll
        for (int t = 0; t < 8; t++) {           // A: 2048 chunks (128 rows x 16)
            int idx = tid + t * 256;
            int r = idx >> 4, c16 = idx & 15;
            size_t so = ((size_t)(m0 + r) * 256 + c * 128 + c16 * 8) * 2;
            cpa16(st + T2_A + (uint32_t)(r * 136 + c16 * 8) * 2, (const unsigned char*)g_h16 + so);
        }
        #pragma unroll
        for (int t = 0; t < 3; t++) {           // B: 768 chunks (128 k-rows x 6)
            int idx = tid + t * 256;
            int kr = idx / 6, c6 = idx - kr * 6;
            size_t so = ((size_t)(c * 128 + kr) * 48 + c6 * 8) * 2;
            cpa16(st + T2_B + (uint32_t)(kr * 56 + c6 * 8) * 2, (const unsigned char*)g_B2f + so);
        }
        CP_COMMIT();
    }

    int wid = tid >> 5;                          // warp tile 16 x 48

    wmma::fragment<wmma::accumulator, 16, 16, 16, float> acc[3];
    #pragma unroll
    for (int j = 0; j < 3; j++) wmma::fill_fragment(acc[j], 0.f);

    CP_WAIT1();
    __syncthreads();

    #pragma unroll
    for (int c = 0; c < 2; c++) {
        const unsigned char* st = smem + c * T2_STAGE;
        const __half* A_ = (const __half*)(st + T2_A);
        const __half* B_ = (const __half*)(st + T2_B);
        #pragma unroll
        for (int k16 = 0; k16 < 8; k16++) {
            wmma::fragment<wmma::matrix_a, 16, 16, 16, __half, wmma::row_major> af;
            wmma::fragment<wmma::matrix_b, 16, 16, 16, __half, wmma::row_major> bfr[3];
            wmma::load_matrix_sync(af, A_ + (wid * 16) * 136 + k16 * 16, 136);
            #pragma unroll
            for (int j = 0; j < 3; j++)
                wmma::load_matrix_sync(bfr[j], B_ + (k16 * 16) * 56 + j * 16, 56);
            #pragma unroll
            for (int j = 0; j < 3; j++)
                wmma::mma_sync(acc[j], af, bfr[j], acc[j]);
        }
        if (c == 0) { CP_WAIT0(); __syncthreads(); }
    }

    __syncthreads();
    float* tile = (float*)smem;
    #pragma unroll
    for (int j = 0; j < 3; j++)
        wmma::store_matrix_sync(&tile[(wid * 16) * 56 + j * 16], acc[j], 56, wmma::mem_row_major);
    __syncthreads();

    #pragma unroll
    for (int t = 0; t < 6; t++) {               // fp16 Wh2 store
        int idx = tid + t * 256;
        int r = idx / 12, c4 = idx - r * 12;
        float4 v = *(const float4*)&tile[r * 56 + c4 * 4];
        __half2 p0 = __floats2half2_rn(v.x, v.y);
        __half2 p1 = __floats2half2_rn(v.z, v.w);
        uint2 o = make_uint2(*(uint32_t*)&p0, *(uint32_t*)&p1);
        *(uint2*)&g_Wh2h[(size_t)(m0 + r) * 48 + c4 * 4] = o;
    }
    if (tid < 128) {
        int row = tid;
        const float* rp = &tile[row * 56];
        float sr = 0.f, sc = 0.f;
        #pragma unroll
        for (int q = 0; q < 10; q++) {
            float4 v  = *(const float4*)&rp[q * 4];
            float4 ar = __ldg((const float4*)&aout[q * 4]);
            float4 ac = __ldg((const float4*)&aout[40 + q * 4]);
            sr += v.x * ar.x + v.y * ar.y + v.z * ar.z + v.w * ar.w;
            sc += v.x * ac.x + v.y * ac.y + v.z * ac.z + v.w * ac.w;
        }
        int gr = m0 + row;
        if (gr < NN) { g_s2r[gr] = sr; g_s2c[gr] = sc; }
    }
}

// ---------------- layer1 aggregation (warp per node, fp16 gathers); emits h fp16 ----------------
__global__ void k_gat1() {
    int gw = (blockIdx.x * blockDim.x + threadIdx.x) >> 5;
    int lane = threadIdx.x & 31;
    if (gw >= NN) return;
    const float4 sr = *(const float4*)&g_s1r[gw * 4];
    int beg = g_off[gw], end = g_off[gw + 1];

    float4 acc0 = make_float4(0.f, 0.f, 0.f, 0.f);
    float4 acc1 = make_float4(0.f, 0.f, 0.f, 0.f);
    float d0 = 0.f, d1 = 0.f, d2 = 0.f, d3 = 0.f;

    for (int base = beg; base < end; base += 32) {
        int e = base + lane;
        int j = 0; float ex0 = 0.f, ex1 = 0.f, ex2 = 0.f, ex3 = 0.f;
        if (e < end) {
            j = __ldg(&g_csr[e]);
            float4 s = __ldg((const float4*)&g_s1c[j * 4]);
            ex0 = __expf(lrelu(sr.x + s.x));
            ex1 = __expf(lrelu(sr.y + s.y));
            ex2 = __expf(lrelu(sr.z + s.z));
            ex3 = __expf(lrelu(sr.w + s.w));
            d0 += ex0; d1 += ex1; d2 += ex2; d3 += ex3;
        }
        int cnt = min(32, end - base);
        for (int k = 0; k < cnt; k++) {
            int   jj = __shfl_sync(0xffffffffu, j,   k);
            float w0 = __shfl_sync(0xffffffffu, ex0, k);
            float w1 = __shfl_sync(0xffffffffu, ex1, k);
            float w2 = __shfl_sync(0xffffffffu, ex2, k);
            float w3 = __shfl_sync(0xffffffffu, ex3, k);
            const __half* wp = &g_Wh1h[(size_t)jj * 256];
            uint2 q0 = __ldg((const uint2*)(wp + 4 * lane));
            uint2 q1 = __ldg((const uint2*)(wp + 128 + 4 * lane));
            float2 f0 = __half22float2(*(__half2*)&q0.x);
            float2 f1 = __half22float2(*(__half2*)&q0.y);
            float2 f2 = __half22float2(*(__half2*)&q1.x);
            float2 f3 = __half22float2(*(__half2*)&q1.y);
            float wa = (lane < 16) ? w0 : w1;
            float wb = (lane < 16) ? w2 : w3;
            acc0.x += wa * f0.x; acc0.y += wa * f0.y; acc0.z += wa * f1.x; acc0.w += wa * f1.y;
            acc1.x += wb * f2.x; acc1.y += wb * f2.y; acc1.z += wb * f3.x; acc1.w += wb * f3.y;
        }
    }
    d0 = wsum(d0); d1 = wsum(d1); d2 = wsum(d2); d3 = wsum(d3);
    float inva = (lane < 16) ? (1.f / d0) : (1.f / d1);
    float invb = (lane < 16) ? (1.f / d2) : (1.f / d3);

    __half2 h00 = __floats2half2_rn(elu(acc0.x * inva), elu(acc0.y * inva));
    __half2 h01 = __floats2half2_rn(elu(acc0.z * inva), elu(acc0.w * inva));
    __half2 h10 = __floats2half2_rn(elu(acc1.x * invb), elu(acc1.y * invb));
    __half2 h11 = __floats2half2_rn(elu(acc1.z * invb), elu(acc1.w * invb));
    *(uint2*)&g_h16[(size_t)gw * 256 + 4 * lane]       = make_uint2(*(uint32_t*)&h00, *(uint32_t*)&h01);
    *(uint2*)&g_h16[(size_t)gw * 256 + 128 + 4 * lane] = make_uint2(*(uint32_t*)&h10, *(uint32_t*)&h11);
}

// ---------------- layer2 attention + ELU + log_softmax (fp16 gathers) ----------------
__global__ void k_gat2(float* __restrict__ out) {
    int gw = (blockIdx.x * blockDim.x + threadIdx.x) >> 5;
    int lane = threadIdx.x & 31;
    if (gw >= NN) return;
    float s2v = __ldg(&g_s2r[gw]);
    int beg = g_off[gw], end = g_off[gw + 1];
    int half = lane >> 4, sl = lane & 15;

    float4 acc = make_float4(0.f, 0.f, 0.f, 0.f);
    float den = 0.f;
    for (int base = beg; base < end; base += 32) {
        int e = base + lane;
        int j = 0; float ex = 0.f;
        if (e < end) {
            j = __ldg(&g_csr[e]);
            ex = __expf(lrelu(s2v + __ldg(&g_s2c[j])));
            den += ex;
        }
        int cnt = min(32, end - base);
        for (int k = 0; k < cnt; k += 2) {
            int kk = k + half;
            int src = (kk < cnt) ? kk : k;
            int   jj = __shfl_sync(0xffffffffu, j,  src);
            float w  = __shfl_sync(0xffffffffu, ex, src);
            if (kk >= cnt) w = 0.f;
            if (sl < 10) {
                uint2 q = __ldg((const uint2*)&g_Wh2h[(size_t)jj * 48 + 4 * sl]);
                float2 f0 = __half22float2(*(__half2*)&q.x);
                float2 f1 = __half22float2(*(__half2*)&q.y);
                acc.x += w * f0.x; acc.y += w * f0.y; acc.z += w * f1.x; acc.w += w * f1.y;
            }
        }
    }
    acc.x += __shfl_xor_sync(0xffffffffu, acc.x, 16);
    acc.y += __shfl_xor_sync(0xffffffffu, acc.y, 16);
    acc.z += __shfl_xor_sync(0xffffffffu, acc.z, 16);
    acc.w += __shfl_xor_sync(0xffffffffu, acc.w, 16);
    den = wsum(den);
    float inv = 1.f / den;
    bool valid = (lane < 10);
    float o0 = -1e30f, o1 = -1e30f, o2 = -1e30f, o3 = -1e30f;
    if (valid) {
        o0 = elu(acc.x * inv); o1 = elu(acc.y * inv);
        o2 = elu(acc.z * inv); o3 = elu(acc.w * inv);
    }
    float mm = wmax(fmaxf(fmaxf(o0, o1), fmaxf(o2, o3)));
    float se = 0.f;
    if (valid) se = __expf(o0 - mm) + __expf(o1 - mm) + __expf(o2 - mm) + __expf(o3 - mm);
    se = wsum(se);
    float L = mm + logf(se);
    if (valid)
        *(float4*)&out[(size_t)gw * NCLASS + 4 * lane] = make_float4(o0 - L, o1 - L, o2 - L, o3 - L);
}

// ---------------- launch ----------------
extern "C" void kernel_launch(void* const* d_in, const int* in_sizes, int n_in,
                              void* d_out, int out_size) {
    const float* x    = (const float*)d_in[0];
    const float* W    = (const float*)d_in[1];
    const float* a    = (const float*)d_in[2];
    const float* Wout = (const float*)d_in[3];
    const float* aout = (const float*)d_in[4];
    const int*   row  = (const int*)d_in[5];
    const int*   col  = (const int*)d_in[6];
    int E = in_sizes[5];
    float* out = (float*)d_out;

    static cudaStream_t s2 = nullptr;
    static cudaEvent_t evF = nullptr, evJ = nullptr;
    if (!s2) {
        cudaStreamCreateWithFlags(&s2, cudaStreamNonBlocking);
        cudaEventCreateWithFlags(&evF, cudaEventDisableTiming);
        cudaEventCreateWithFlags(&evJ, cudaEventDisableTiming);
        cudaFuncSetAttribute(k_gemm1, cudaFuncAttributeMaxDynamicSharedMemorySize, T1_BYTES);
        cudaFuncSetAttribute(k_gemm2, cudaFuncAttributeMaxDynamicSharedMemorySize, T2_BYTES);
    }

    // fork CSR chain immediately
    cudaEventRecord(evF, 0);
    cudaStreamWaitEvent(s2, evF, 0);
    k_zero <<<(NN + 255) / 256, 256, 0, s2>>>();
    k_count<<<(E + 255) / 256, 256, 0, s2>>>(row, E);

    k_prep<<<1280, 256>>>(x, W, Wout);
    k_gemm1<<<NTILE, 256, T1_BYTES>>>(a);              // profiled slot

    k_scan1<<<NB1, SB, 0, s2>>>();
    k_scan2<<<1, 256, 0, s2>>>();
    k_scan3<<<NB1, SB, 0, s2>>>(E);
    k_fill <<<(E + 255) / 256, 256, 0, s2>>>(row, col, E);

    cudaEventRecord(evJ, s2);
    cudaStreamWaitEvent(0, evJ, 0);

    k_gat1<<<(NN + 7) / 8, 256>>>();
    k_gemm2<<<NTILE, 256, T2_BYTES>>>(aout);
    k_gat2<<<(NN + 7) / 8, 256>>>(out);
}

// round 11
// speedup vs baseline: 1.7827x; 1.1329x over previous
#include <cuda_runtime.h>
#include <cuda_bf16.h>
#include <cuda_fp16.h>
#include <mma.h>
#include <math.h>
#include <stdint.h>

using namespace nvcuda;

// Problem constants
#define NN      100000
#define EMAX    1700000
#define NCLASS  40
#define SB      512
#define NB1     ((NN + SB - 1) / SB)
#define NTILE   782                    // ceil(NN/128)
#define NPAD    (NTILE * 128)          // 100096

// ---------------- scratch (static device globals) ----------------
__device__ __align__(16) __half g_Wh1h[(size_t)NPAD * 256];  // layer1 Wh fp16 (gather source)
__device__ __align__(16) __half g_Wh2h[(size_t)NPAD * 48];   // layer2 Wh fp16, ld=48
__device__ __align__(16) __half g_h16[(size_t)NPAD * 256];   // layer1 output fp16 (gemm2 A)
__device__ float g_s1r[NN * 4];
__device__ float g_s1c[NN * 4];
__device__ float g_s2r[NN];
__device__ float g_s2c[NN];
__device__ int   g_deg[NN];
__device__ int   g_cur[NN];
__device__ int   g_off[NN + 1];
__device__ int   g_csr[EMAX];
__device__ int   g_bsum[256];
__device__ int   g_boff[256];
// operands
__device__ __align__(16) __half g_x16[(size_t)NPAD * 128];   // x fp16
__device__ __align__(16) __half g_B1f[128 * 256];            // B1 fp16 [k][n] ld 256
__device__ __align__(16) __half g_B2f[256 * 48];             // B2 fp16 [k][n] ld 48 (n>=40 zero)

// ---------------- helpers ----------------
__device__ __forceinline__ uint32_t smem_u32(const void* p) {
    uint32_t a;
    asm("{ .reg .u64 t; cvta.to.shared.u64 t, %1; cvt.u32.u64 %0, t; }" : "=r"(a) : "l"(p));
    return a;
}
__device__ __forceinline__ void cpa16(uint32_t dst, const void* src) {
    asm volatile("cp.async.cg.shared.global [%0], [%1], 16;" :: "r"(dst), "l"(src));
}
#define CP_COMMIT() asm volatile("cp.async.commit_group;" ::: "memory")
#define CP_WAIT1()  asm volatile("cp.async.wait_group 1;" ::: "memory")
#define CP_WAIT0()  asm volatile("cp.async.wait_group 0;" ::: "memory")

__device__ __forceinline__ float wmax(float v) {
    #pragma unroll
    for (int o = 16; o; o >>= 1) v = fmaxf(v, __shfl_xor_sync(0xffffffffu, v, o));
    return v;
}
__device__ __forceinline__ float wsum(float v) {
    #pragma unroll
    for (int o = 16; o; o >>= 1) v += __shfl_xor_sync(0xffffffffu, v, o);
    return v;
}
__device__ __forceinline__ float lrelu(float v) { return v > 0.f ? v : 0.1f * v; }
__device__ __forceinline__ float elu(float v)   { return v > 0.f ? v : expm1f(v); }

// ---------------- prep: x/B1/B2 -> fp16, zero h16 pad rows ----------------
#define XIT 3200000   // NN*128/4 float4 items
#define PB1 32768
#define PB2 12288
#define PZH 3072      // pad rows of g_h16: 96*256 halves = 3072 uint4
__global__ void k_prep(const float* __restrict__ x, const float* __restrict__ W,
                       const float* __restrict__ Wout) {
    int stride = gridDim.x * blockDim.x;
    for (int i = blockIdx.x * blockDim.x + threadIdx.x; i < XIT + PB1 + PB2 + PZH; i += stride) {
        if (i < XIT) {
            int r = i >> 5, kq = (i & 31) * 4;
            float4 v = __ldg((const float4*)&x[(size_t)r * 128 + kq]);
            __half2 p0 = __floats2half2_rn(v.x, v.y);
            __half2 p1 = __floats2half2_rn(v.z, v.w);
            uint2 o = make_uint2(*(uint32_t*)&p0, *(uint32_t*)&p1);
            *(uint2*)&g_x16[(size_t)r * 128 + kq] = o;
        } else if (i < XIT + PB1) {
            int i2 = i - XIT;
            int k = i2 >> 8, n = i2 & 255;
            float v = W[(n >> 6) * 8192 + k * 64 + (n & 63)];
            g_B1f[i2] = __float2half_rn(v);
        } else if (i < XIT + PB1 + PB2) {
            int j = i - XIT - PB1;
            int k = j / 48, n = j - k * 48;
            float v = (n < NCLASS) ? Wout[k * NCLASS + n] : 0.f;
            g_B2f[j] = __float2half_rn(v);
        } else {
            int j = i - XIT - PB1 - PB2;
            *(uint4*)((unsigned char*)g_h16 + (size_t)NN * 512 + (size_t)j * 16) =
                make_uint4(0, 0, 0, 0);
        }
    }
}

// ---------------- CSR build ----------------
__global__ void k_zero() {
    int i = blockIdx.x * blockDim.x + threadIdx.x;
    if (i < NN) { g_deg[i] = 0; g_cur[i] = 0; }
}
__global__ void k_count(const int* __restrict__ row, int E) {
    int e = blockIdx.x * blockDim.x + threadIdx.x;
    if (e < E) atomicAdd(&g_deg[__ldg(&row[e])], 1);
}
__global__ void k_scan1() {
    __shared__ int s[SB];
    int tid = threadIdx.x, g = blockIdx.x * SB + tid;
    int v = (g < NN) ? g_deg[g] : 0;
    s[tid] = v; __syncthreads();
    for (int o = 1; o < SB; o <<= 1) {
        int t = (tid >= o) ? s[tid - o] : 0;
        __syncthreads(); s[tid] += t; __syncthreads();
    }
    if (g < NN) g_off[g] = s[tid] - v;
    if (tid == SB - 1) g_bsum[blockIdx.x] = s[tid];
}
__global__ void k_scan2() {
    __shared__ int s[256];
    int tid = threadIdx.x;
    int v = (tid < NB1) ? g_bsum[tid] : 0;
    s[tid] = v; __syncthreads();
    for (int o = 1; o < 256; o <<= 1) {
        int t = (tid >= o) ? s[tid - o] : 0;
        __syncthreads(); s[tid] += t; __syncthreads();
    }
    g_boff[tid] = s[tid] - v;
}
__global__ void k_scan3(int E) {
    int tid = threadIdx.x, g = blockIdx.x * SB + tid;
    if (g < NN) g_off[g] += g_boff[blockIdx.x];
    if (g == 0) g_off[NN] = E;
}
__global__ void k_fill(const int* __restrict__ row, const int* __restrict__ col, int E) {
    int e = blockIdx.x * blockDim.x + threadIdx.x;
    if (e >= E) return;
    int r = __ldg(&row[e]);
    int p = g_off[r] + atomicAdd(&g_cur[r], 1);
    g_csr[p] = __ldg(&col[e]);
}

// ---------------- GEMM1: Wh1 = x @ B1 [128x128 CTA tile, K=128, 2 CTAs/SM, fused s1] ----------------
// grid (NTILE, 2). stage: A(128x64 ld72)=18432B + B(64x128 ld136)=17408B = 35840B; x2 = 71680.
// epilogue fp32 tile ld132 = 67584 <= 71680 (reuses stage region after MMA).
#define G1_STAGE 35840
#define G1_BOFF  18432
#define T1_BYTES 71680

__global__ __launch_bounds__(256, 2) void k_gemm1(const float* __restrict__ a) {
    extern __shared__ __align__(16) unsigned char smem[];
    uint32_t sbase = smem_u32(smem);
    int tid = threadIdx.x;
    int m0 = blockIdx.x * 128;
    int n0 = blockIdx.y * 128;

    #pragma unroll
    for (int c = 0; c < 2; c++) {
        uint32_t st = sbase + c * G1_STAGE;
        #pragma unroll
        for (int t = 0; t < 4; t++) {           // A: 1024 chunks (128 rows x 8)
            int idx = tid + t * 256;
            int r = idx >> 3, c8 = idx & 7;
            size_t so = ((size_t)(m0 + r) * 128 + c * 64 + c8 * 8) * 2;
            cpa16(st + (uint32_t)(r * 72 + c8 * 8) * 2, (const unsigned char*)g_x16 + so);
        }
        #pragma unroll
        for (int t = 0; t < 4; t++) {           // B: 1024 chunks (64 k-rows x 16)
            int idx = tid + t * 256;
            int kr = idx >> 4, c16 = idx & 15;
            size_t so = ((size_t)(c * 64 + kr) * 256 + n0 + c16 * 8) * 2;
            cpa16(st + G1_BOFF + (uint32_t)(kr * 136 + c16 * 8) * 2, (const unsigned char*)g_B1f + so);
        }
        CP_COMMIT();
    }

    int wid = tid >> 5, wm = wid & 3, wn = wid >> 2;  // 4M x 2N warps, tile 32x64

    wmma::fragment<wmma::accumulator, 16, 16, 16, float> acc[2][4];
    #pragma unroll
    for (int i = 0; i < 2; i++)
        #pragma unroll
        for (int j = 0; j < 4; j++) wmma::fill_fragment(acc[i][j], 0.f);

    CP_WAIT1();
    __syncthreads();

    #pragma unroll
    for (int c = 0; c < 2; c++) {
        const __half* A_ = (const __half*)(smem + c * G1_STAGE);
        const __half* B_ = (const __half*)(smem + c * G1_STAGE + G1_BOFF);
        #pragma unroll
        for (int k8 = 0; k8 < 4; k8++) {
            wmma::fragment<wmma::matrix_a, 16, 16, 16, __half, wmma::row_major> af[2];
            wmma::fragment<wmma::matrix_b, 16, 16, 16, __half, wmma::row_major> bfr[4];
            #pragma unroll
            for (int i = 0; i < 2; i++)
                wmma::load_matrix_sync(af[i], A_ + (wm * 32 + i * 16) * 72 + k8 * 16, 72);
            #pragma unroll
            for (int j = 0; j < 4; j++)
                wmma::load_matrix_sync(bfr[j], B_ + (k8 * 16) * 136 + wn * 64 + j * 16, 136);
            #pragma unroll
            for (int i = 0; i < 2; i++)
                #pragma unroll
                for (int j = 0; j < 4; j++)
                    wmma::mma_sync(acc[i][j], af[i], bfr[j], acc[i][j]);
        }
        if (c == 0) { CP_WAIT0(); __syncthreads(); }
    }

    // epilogue: fp32 tile ld 132 in smem, fp16 Wh1 write + fused s1 (this CTA owns 2 heads)
    __syncthreads();
    float* tile = (float*)smem;
    #pragma unroll
    for (int i = 0; i < 2; i++)
        #pragma unroll
        for (int j = 0; j < 4; j++)
            wmma::store_matrix_sync(&tile[(wm * 32 + i * 16) * 132 + wn * 64 + j * 16],
                                    acc[i][j], 132, wmma::mem_row_major);
    __syncthreads();

    // Wh1h write: 2048 uint4 (128 rows x 16)
    #pragma unroll
    for (int t = 0; t < 8; t++) {
        int idx = tid + t * 256;
        int r = idx >> 4, c8 = (idx & 15) * 8;
        if (m0 + r < NN) {
            float4 v0 = *(const float4*)&tile[r * 132 + c8];
            float4 v1 = *(const float4*)&tile[r * 132 + c8 + 4];
            __half2 p0 = __floats2half2_rn(v0.x, v0.y);
            __half2 p1 = __floats2half2_rn(v0.z, v0.w);
            __half2 p2 = __floats2half2_rn(v1.x, v1.y);
            __half2 p3 = __floats2half2_rn(v1.z, v1.w);
            uint4 o = make_uint4(*(uint32_t*)&p0, *(uint32_t*)&p1,
                                 *(uint32_t*)&p2, *(uint32_t*)&p3);
            *(uint4*)&g_Wh1h[(size_t)(m0 + r) * 256 + n0 + c8] = o;
        }
    }
    // fused s1: thread (row = tid>>1, local head = tid&1)
    {
        int hl = tid & 1;
        int row = tid >> 1;
        int hg = (n0 >> 6) + hl;
        const float* rp = &tile[row * 132 + hl * 64];
        float sr = 0.f, sc = 0.f;
        #pragma unroll
        for (int q = 0; q < 16; q++) {
            float4 v  = *(const float4*)&rp[q * 4];
            float4 ar = __ldg((const float4*)&a[hg * 128 + q * 4]);
            float4 ac = __ldg((const float4*)&a[hg * 128 + 64 + q * 4]);
            sr += v.x * ar.x + v.y * ar.y + v.z * ar.z + v.w * ar.w;
            sc += v.x * ac.x + v.y * ac.y + v.z * ac.z + v.w * ac.w;
        }
        int gr = m0 + row;
        if (gr < NN) {
            g_s1r[gr * 4 + hg] = sr;
            g_s1c[gr * 4 + hg] = sc;
        }
    }
}

// ---------------- GEMM2: Wh2 = h16 @ B2 [128x48, K=256, fp16 single-pass, fused s2] ----------------
#define T2_A 0
#define T2_B 34816
#define T2_STAGE 49152
#define T2_BYTES (2 * T2_STAGE)

__global__ __launch_bounds__(256) void k_gemm2(const float* __restrict__ aout) {
    extern __shared__ __align__(16) unsigned char smem[];
    uint32_t sbase = smem_u32(smem);
    int tid = threadIdx.x;
    int m0 = blockIdx.x * 128;

    #pragma unroll
    for (int c = 0; c < 2; c++) {
        uint32_t st = sbase + c * T2_STAGE;
        #pragma unroll
        for (int t = 0; t < 8; t++) {           // A: 2048 chunks (128 rows x 16)
            int idx = tid + t * 256;
            int r = idx >> 4, c16 = idx & 15;
            size_t so = ((size_t)(m0 + r) * 256 + c * 128 + c16 * 8) * 2;
            cpa16(st + T2_A + (uint32_t)(r * 136 + c16 * 8) * 2, (const unsigned char*)g_h16 + so);
        }
        #pragma unroll
        for (int t = 0; t < 3; t++) {           // B: 768 chunks (128 k-rows x 6)
            int idx = tid + t * 256;
            int kr = idx / 6, c6 = idx - kr * 6;
            size_t so = ((size_t)(c * 128 + kr) * 48 + c6 * 8) * 2;
            cpa16(st + T2_B + (uint32_t)(kr * 56 + c6 * 8) * 2, (const unsigned char*)g_B2f + so);
        }
        CP_COMMIT();
    }

    int wid = tid >> 5;                          // warp tile 16 x 48

    wmma::fragment<wmma::accumulator, 16, 16, 16, float> acc[3];
    #pragma unroll
    for (int j = 0; j < 3; j++) wmma::fill_fragment(acc[j], 0.f);

    CP_WAIT1();
    __syncthreads();

    #pragma unroll
    for (int c = 0; c < 2; c++) {
        const unsigned char* st = smem + c * T2_STAGE;
        const __half* A_ = (const __half*)(st + T2_A);
        const __half* B_ = (const __half*)(st + T2_B);
        #pragma unroll
        for (int k16 = 0; k16 < 8; k16++) {
            wmma::fragment<wmma::matrix_a, 16, 16, 16, __half, wmma::row_major> af;
            wmma::fragment<wmma::matrix_b, 16, 16, 16, __half, wmma::row_major> bfr[3];
            wmma::load_matrix_sync(af, A_ + (wid * 16) * 136 + k16 * 16, 136);
            #pragma unroll
            for (int j = 0; j < 3; j++)
                wmma::load_matrix_sync(bfr[j], B_ + (k16 * 16) * 56 + j * 16, 56);
            #pragma unroll
            for (int j = 0; j < 3; j++)
                wmma::mma_sync(acc[j], af, bfr[j], acc[j]);
        }
        if (c == 0) { CP_WAIT0(); __syncthreads(); }
    }

    __syncthreads();
    float* tile = (float*)smem;
    #pragma unroll
    for (int j = 0; j < 3; j++)
        wmma::store_matrix_sync(&tile[(wid * 16) * 56 + j * 16], acc[j], 56, wmma::mem_row_major);
    __syncthreads();

    #pragma unroll
    for (int t = 0; t < 6; t++) {               // fp16 Wh2 store
        int idx = tid + t * 256;
        int r = idx / 12, c4 = idx - r * 12;
        float4 v = *(const float4*)&tile[r * 56 + c4 * 4];
        __half2 p0 = __floats2half2_rn(v.x, v.y);
        __half2 p1 = __floats2half2_rn(v.z, v.w);
        uint2 o = make_uint2(*(uint32_t*)&p0, *(uint32_t*)&p1);
        *(uint2*)&g_Wh2h[(size_t)(m0 + r) * 48 + c4 * 4] = o;
    }
    if (tid < 128) {
        int row = tid;
        const float* rp = &tile[row * 56];
        float sr = 0.f, sc = 0.f;
        #pragma unroll
        for (int q = 0; q < 10; q++) {
            float4 v  = *(const float4*)&rp[q * 4];
            float4 ar = __ldg((const float4*)&aout[q * 4]);
            float4 ac = __ldg((const float4*)&aout[40 + q * 4]);
            sr += v.x * ar.x + v.y * ar.y + v.z * ar.z + v.w * ar.w;
            sc += v.x * ac.x + v.y * ac.y + v.z * ac.z + v.w * ac.w;
        }
        int gr = m0 + row;
        if (gr < NN) { g_s2r[gr] = sr; g_s2c[gr] = sc; }
    }
}

// ---------------- layer1 aggregation: lane = 8 cols; 1 LDG.128/edge; smem broadcast ----------------
__global__ __launch_bounds__(256) void k_gat1() {
    __shared__ float4 sEx[8][32];
    __shared__ int    sJ[8][32];
    int w = threadIdx.x >> 5;
    int gw = (blockIdx.x * blockDim.x + threadIdx.x) >> 5;
    int lane = threadIdx.x & 31;
    if (gw >= NN) return;
    const float4 sr = *(const float4*)&g_s1r[gw * 4];
    int beg = g_off[gw], end = g_off[gw + 1];
    int hsel = lane >> 3;                         // head owned by this lane (8 cols each)

    float acc0 = 0.f, acc1 = 0.f, acc2 = 0.f, acc3 = 0.f;
    float acc4 = 0.f, acc5 = 0.f, acc6 = 0.f, acc7 = 0.f;
    float d0 = 0.f, d1 = 0.f, d2 = 0.f, d3 = 0.f;

    for (int base = beg; base < end; base += 32) {
        int e = base + lane;
        int j = 0;
        float4 ex = make_float4(0.f, 0.f, 0.f, 0.f);
        if (e < end) {
            j = __ldg(&g_csr[e]);
            float4 s = __ldg((const float4*)&g_s1c[j * 4]);
            ex.x = __expf(lrelu(sr.x + s.x));
            ex.y = __expf(lrelu(sr.y + s.y));
            ex.z = __expf(lrelu(sr.z + s.z));
            ex.w = __expf(lrelu(sr.w + s.w));
            d0 += ex.x; d1 += ex.y; d2 += ex.z; d3 += ex.w;
        }
        sEx[w][lane] = ex;
        sJ[w][lane] = j;
        __syncwarp();
        int cnt = min(32, end - base);
        for (int k = 0; k < cnt; k++) {
            float4 e4 = sEx[w][k];                 // smem broadcast (conflict-free)
            int jj = sJ[w][k];
            float wt = (hsel & 2) ? ((hsel & 1) ? e4.w : e4.z)
                                  : ((hsel & 1) ? e4.y : e4.x);
            uint4 q = __ldg((const uint4*)&g_Wh1h[(size_t)jj * 256 + 8 * lane]);
            float2 f0 = __half22float2(*(__half2*)&q.x);
            float2 f1 = __half22float2(*(__half2*)&q.y);
            float2 f2 = __half22float2(*(__half2*)&q.z);
            float2 f3 = __half22float2(*(__half2*)&q.w);
            acc0 += wt * f0.x; acc1 += wt * f0.y;
            acc2 += wt * f1.x; acc3 += wt * f1.y;
            acc4 += wt * f2.x; acc5 += wt * f2.y;
            acc6 += wt * f3.x; acc7 += wt * f3.y;
        }
        __syncwarp();
    }
    d0 = wsum(d0); d1 = wsum(d1); d2 = wsum(d2); d3 = wsum(d3);
    float inv = (hsel & 2) ? ((hsel & 1) ? 1.f / d3 : 1.f / d2)
                           : ((hsel & 1) ? 1.f / d1 : 1.f / d0);

    __half2 o0 = __floats2half2_rn(elu(acc0 * inv), elu(acc1 * inv));
    __half2 o1 = __floats2half2_rn(elu(acc2 * inv), elu(acc3 * inv));
    __half2 o2 = __floats2half2_rn(elu(acc4 * inv), elu(acc5 * inv));
    __half2 o3 = __floats2half2_rn(elu(acc6 * inv), elu(acc7 * inv));
    uint4 o = make_uint4(*(uint32_t*)&o0, *(uint32_t*)&o1,
                         *(uint32_t*)&o2, *(uint32_t*)&o3);
    *(uint4*)&g_h16[(size_t)gw * 256 + 8 * lane] = o;
}

// ---------------- layer2 attention + ELU + log_softmax (fp16 gathers) ----------------
__global__ void k_gat2(float* __restrict__ out) {
    int gw = (blockIdx.x * blockDim.x + threadIdx.x) >> 5;
    int lane = threadIdx.x & 31;
    if (gw >= NN) return;
    float s2v = __ldg(&g_s2r[gw]);
    int beg = g_off[gw], end = g_off[gw + 1];
    int half = lane >> 4, sl = lane & 15;

    float4 acc = make_float4(0.f, 0.f, 0.f, 0.f);
    float den = 0.f;
    for (int base = beg; base < end; base += 32) {
        int e = base + lane;
        int j = 0; float ex = 0.f;
        if (e < end) {
            j = __ldg(&g_csr[e]);
            ex = __expf(lrelu(s2v + __ldg(&g_s2c[j])));
            den += ex;
        }
        int cnt = min(32, end - base);
        for (int k = 0; k < cnt; k += 2) {
            int kk = k + half;
            int src = (kk < cnt) ? kk : k;
            int   jj = __shfl_sync(0xffffffffu, j,  src);
            float w  = __shfl_sync(0xffffffffu, ex, src);
            if (kk >= cnt) w = 0.f;
            if (sl < 10) {
                uint2 q = __ldg((const uint2*)&g_Wh2h[(size_t)jj * 48 + 4 * sl]);
                float2 f0 = __half22float2(*(__half2*)&q.x);
                float2 f1 = __half22float2(*(__half2*)&q.y);
                acc.x += w * f0.x; acc.y += w * f0.y; acc.z += w * f1.x; acc.w += w * f1.y;
            }
        }
    }
    acc.x += __shfl_xor_sync(0xffffffffu, acc.x, 16);
    acc.y += __shfl_xor_sync(0xffffffffu, acc.y, 16);
    acc.z += __shfl_xor_sync(0xffffffffu, acc.z, 16);
    acc.w += __shfl_xor_sync(0xffffffffu, acc.w, 16);
    den = wsum(den);
    float inv = 1.f / den;
    bool valid = (lane < 10);
    float o0 = -1e30f, o1 = -1e30f, o2 = -1e30f, o3 = -1e30f;
    if (valid) {
        o0 = elu(acc.x * inv); o1 = elu(acc.y * inv);
        o2 = elu(acc.z * inv); o3 = elu(acc.w * inv);
    }
    float mm = wmax(fmaxf(fmaxf(o0, o1), fmaxf(o2, o3)));
    float se = 0.f;
    if (valid) se = __expf(o0 - mm) + __expf(o1 - mm) + __expf(o2 - mm) + __expf(o3 - mm);
    se = wsum(se);
    float L = mm + logf(se);
    if (valid)
        *(float4*)&out[(size_t)gw * NCLASS + 4 * lane] = make_float4(o0 - L, o1 - L, o2 - L, o3 - L);
}

// ---------------- launch ----------------
extern "C" void kernel_launch(void* const* d_in, const int* in_sizes, int n_in,
                              void* d_out, int out_size) {
    const float* x    = (const float*)d_in[0];
    const float* W    = (const float*)d_in[1];
    const float* a    = (const float*)d_in[2];
    const float* Wout = (const float*)d_in[3];
    const float* aout = (const float*)d_in[4];
    const int*   row  = (const int*)d_in[5];
    const int*   col  = (const int*)d_in[6];
    int E = in_sizes[5];
    float* out = (float*)d_out;

    static cudaStream_t s2 = nullptr;
    static cudaEvent_t evF = nullptr, evJ = nullptr;
    if (!s2) {
        cudaStreamCreateWithFlags(&s2, cudaStreamNonBlocking);
        cudaEventCreateWithFlags(&evF, cudaEventDisableTiming);
        cudaEventCreateWithFlags(&evJ, cudaEventDisableTiming);
        cudaFuncSetAttribute(k_gemm1, cudaFuncAttributeMaxDynamicSharedMemorySize, T1_BYTES);
        cudaFuncSetAttribute(k_gemm2, cudaFuncAttributeMaxDynamicSharedMemorySize, T2_BYTES);
    }

    // fork CSR chain immediately
    cudaEventRecord(evF, 0);
    cudaStreamWaitEvent(s2, evF, 0);
    k_zero <<<(NN + 255) / 256, 256, 0, s2>>>();
    k_count<<<(E + 255) / 256, 256, 0, s2>>>(row, E);

    k_prep<<<1280, 256>>>(x, W, Wout);
    k_gemm1<<<dim3(NTILE, 2), 256, T1_BYTES>>>(a);     // profiled slot

    k_scan1<<<NB1, SB, 0, s2>>>();
    k_scan2<<<1, 256, 0, s2>>>();
    k_scan3<<<NB1, SB, 0, s2>>>(E);
    k_fill <<<(E + 255) / 256, 256, 0, s2>>>(row, col, E);

    cudaEventRecord(evJ, s2);
    cudaStreamWaitEvent(0, evJ, 0);

    k_gat1<<<(NN + 7) / 8, 256>>>();
    k_gemm2<<<NTILE, 256, T2_BYTES>>>(aout);
    k_gat2<<<(NN + 7) / 8, 256>>>(out);
}

// round 12
// speedup vs baseline: 1.8966x; 1.0639x over previous
#include <cuda_runtime.h>
#include <cuda_bf16.h>
#include <cuda_fp16.h>
#include <mma.h>
#include <math.h>
#include <stdint.h>

using namespace nvcuda;

// Problem constants
#define NN      100000
#define EMAX    1700000
#define NCLASS  40
#define SB      512
#define NB1     ((NN + SB - 1) / SB)
#define NTILE   782                    // ceil(NN/128)
#define NPAD    (NTILE * 128)          // 100096

// ---------------- scratch (static device globals) ----------------
__device__ __align__(16) __half g_Wh1h[(size_t)NPAD * 256];  // layer1 Wh fp16 (gather source)
__device__ __align__(16) __half g_Wh2h[(size_t)NPAD * 48];   // layer2 Wh fp16, ld=48
__device__ __align__(16) __half g_h16[(size_t)NPAD * 256];   // layer1 output fp16 (gemm2 A)
__device__ float g_s1r[NN * 4];
__device__ float g_s1c[NN * 4];
__device__ float g_s2r[NN];
__device__ float g_s2c[NN];
__device__ int   g_deg[NN];
__device__ int   g_cur[NN];
__device__ int   g_off[NN + 1];
__device__ int   g_csr[EMAX];
__device__ int   g_bsum[256];
__device__ int   g_boff[256];
// operands
__device__ __align__(16) __half g_x16[(size_t)NPAD * 128];   // x fp16
__device__ __align__(16) __half g_B1f[128 * 256];            // B1 fp16 [k][n] ld 256
__device__ __align__(16) __half g_B2f[256 * 48];             // B2 fp16 [k][n] ld 48 (n>=40 zero)

// ---------------- helpers ----------------
__device__ __forceinline__ uint32_t smem_u32(const void* p) {
    uint32_t a;
    asm("{ .reg .u64 t; cvta.to.shared.u64 t, %1; cvt.u32.u64 %0, t; }" : "=r"(a) : "l"(p));
    return a;
}
__device__ __forceinline__ void cpa16(uint32_t dst, const void* src) {
    asm volatile("cp.async.cg.shared.global [%0], [%1], 16;" :: "r"(dst), "l"(src));
}
#define CP_COMMIT() asm volatile("cp.async.commit_group;" ::: "memory")
#define CP_WAIT1()  asm volatile("cp.async.wait_group 1;" ::: "memory")
#define CP_WAIT0()  asm volatile("cp.async.wait_group 0;" ::: "memory")

__device__ __forceinline__ float wmax(float v) {
    #pragma unroll
    for (int o = 16; o; o >>= 1) v = fmaxf(v, __shfl_xor_sync(0xffffffffu, v, o));
    return v;
}
__device__ __forceinline__ float wsum(float v) {
    #pragma unroll
    for (int o = 16; o; o >>= 1) v += __shfl_xor_sync(0xffffffffu, v, o);
    return v;
}
__device__ __forceinline__ float lrelu(float v) { return v > 0.f ? v : 0.1f * v; }
__device__ __forceinline__ float elu(float v)   { return v > 0.f ? v : expm1f(v); }

// ---------------- prep: x/B1/B2 -> fp16, zero h16 pad rows ----------------
#define XIT 3200000   // NN*128/4 float4 items
#define PB1 32768
#define PB2 12288
#define PZH 3072      // pad rows of g_h16: 96*256 halves = 3072 uint4
__global__ void k_prep(const float* __restrict__ x, const float* __restrict__ W,
                       const float* __restrict__ Wout) {
    int stride = gridDim.x * blockDim.x;
    for (int i = blockIdx.x * blockDim.x + threadIdx.x; i < XIT + PB1 + PB2 + PZH; i += stride) {
        if (i < XIT) {
            int r = i >> 5, kq = (i & 31) * 4;
            float4 v = __ldg((const float4*)&x[(size_t)r * 128 + kq]);
            __half2 p0 = __floats2half2_rn(v.x, v.y);
            __half2 p1 = __floats2half2_rn(v.z, v.w);
            uint2 o = make_uint2(*(uint32_t*)&p0, *(uint32_t*)&p1);
            *(uint2*)&g_x16[(size_t)r * 128 + kq] = o;
        } else if (i < XIT + PB1) {
            int i2 = i - XIT;
            int k = i2 >> 8, n = i2 & 255;
            float v = W[(n >> 6) * 8192 + k * 64 + (n & 63)];
            g_B1f[i2] = __float2half_rn(v);
        } else if (i < XIT + PB1 + PB2) {
            int j = i - XIT - PB1;
            int k = j / 48, n = j - k * 48;
            float v = (n < NCLASS) ? Wout[k * NCLASS + n] : 0.f;
            g_B2f[j] = __float2half_rn(v);
        } else {
            int j = i - XIT - PB1 - PB2;
            *(uint4*)((unsigned char*)g_h16 + (size_t)NN * 512 + (size_t)j * 16) =
                make_uint4(0, 0, 0, 0);
        }
    }
}

// ---------------- CSR build ----------------
__global__ void k_zero() {
    int i = blockIdx.x * blockDim.x + threadIdx.x;
    if (i < NN) { g_deg[i] = 0; g_cur[i] = 0; }
}
__global__ void k_count(const int* __restrict__ row, int E) {
    int e = blockIdx.x * blockDim.x + threadIdx.x;
    if (e < E) atomicAdd(&g_deg[__ldg(&row[e])], 1);
}
__global__ void k_scan1() {
    __shared__ int s[SB];
    int tid = threadIdx.x, g = blockIdx.x * SB + tid;
    int v = (g < NN) ? g_deg[g] : 0;
    s[tid] = v; __syncthreads();
    for (int o = 1; o < SB; o <<= 1) {
        int t = (tid >= o) ? s[tid - o] : 0;
        __syncthreads(); s[tid] += t; __syncthreads();
    }
    if (g < NN) g_off[g] = s[tid] - v;
    if (tid == SB - 1) g_bsum[blockIdx.x] = s[tid];
}
__global__ void k_scan2() {
    __shared__ int s[256];
    int tid = threadIdx.x;
    int v = (tid < NB1) ? g_bsum[tid] : 0;
    s[tid] = v; __syncthreads();
    for (int o = 1; o < 256; o <<= 1) {
        int t = (tid >= o) ? s[tid - o] : 0;
        __syncthreads(); s[tid] += t; __syncthreads();
    }
    g_boff[tid] = s[tid] - v;
}
__global__ void k_scan3(int E) {
    int tid = threadIdx.x, g = blockIdx.x * SB + tid;
    if (g < NN) g_off[g] += g_boff[blockIdx.x];
    if (g == 0) g_off[NN] = E;
}
__global__ void k_fill(const int* __restrict__ row, const int* __restrict__ col, int E) {
    int e = blockIdx.x * blockDim.x + threadIdx.x;
    if (e >= E) return;
    int r = __ldg(&row[e]);
    int p = g_off[r] + atomicAdd(&g_cur[r], 1);
    g_csr[p] = __ldg(&col[e]);
}

// ---------------- GEMM1: Wh1 = x @ B1 [128x128 CTA tile, K=128, 2 CTAs/SM, fused s1] ----------------
#define G1_STAGE 35840
#define G1_BOFF  18432
#define T1_BYTES 71680

__global__ __launch_bounds__(256, 2) void k_gemm1(const float* __restrict__ a) {
    extern __shared__ __align__(16) unsigned char smem[];
    uint32_t sbase = smem_u32(smem);
    int tid = threadIdx.x;
    int m0 = blockIdx.x * 128;
    int n0 = blockIdx.y * 128;

    #pragma unroll
    for (int c = 0; c < 2; c++) {
        uint32_t st = sbase + c * G1_STAGE;
        #pragma unroll
        for (int t = 0; t < 4; t++) {           // A: 1024 chunks (128 rows x 8)
            int idx = tid + t * 256;
            int r = idx >> 3, c8 = idx & 7;
            size_t so = ((size_t)(m0 + r) * 128 + c * 64 + c8 * 8) * 2;
            cpa16(st + (uint32_t)(r * 72 + c8 * 8) * 2, (const unsigned char*)g_x16 + so);
        }
        #pragma unroll
        for (int t = 0; t < 4; t++) {           // B: 1024 chunks (64 k-rows x 16)
            int idx = tid + t * 256;
            int kr = idx >> 4, c16 = idx & 15;
            size_t so = ((size_t)(c * 64 + kr) * 256 + n0 + c16 * 8) * 2;
            cpa16(st + G1_BOFF + (uint32_t)(kr * 136 + c16 * 8) * 2, (const unsigned char*)g_B1f + so);
        }
        CP_COMMIT();
    }

    int wid = tid >> 5, wm = wid & 3, wn = wid >> 2;  // 4M x 2N warps, tile 32x64

    wmma::fragment<wmma::accumulator, 16, 16, 16, float> acc[2][4];
    #pragma unroll
    for (int i = 0; i < 2; i++)
        #pragma unroll
        for (int j = 0; j < 4; j++) wmma::fill_fragment(acc[i][j], 0.f);

    CP_WAIT1();
    __syncthreads();

    #pragma unroll
    for (int c = 0; c < 2; c++) {
        const __half* A_ = (const __half*)(smem + c * G1_STAGE);
        const __half* B_ = (const __half*)(smem + c * G1_STAGE + G1_BOFF);
        #pragma unroll
        for (int k8 = 0; k8 < 4; k8++) {
            wmma::fragment<wmma::matrix_a, 16, 16, 16, __half, wmma::row_major> af[2];
            wmma::fragment<wmma::matrix_b, 16, 16, 16, __half, wmma::row_major> bfr[4];
            #pragma unroll
            for (int i = 0; i < 2; i++)
                wmma::load_matrix_sync(af[i], A_ + (wm * 32 + i * 16) * 72 + k8 * 16, 72);
            #pragma unroll
            for (int j = 0; j < 4; j++)
                wmma::load_matrix_sync(bfr[j], B_ + (k8 * 16) * 136 + wn * 64 + j * 16, 136);
            #pragma unroll
            for (int i = 0; i < 2; i++)
                #pragma unroll
                for (int j = 0; j < 4; j++)
                    wmma::mma_sync(acc[i][j], af[i], bfr[j], acc[i][j]);
        }
        if (c == 0) { CP_WAIT0(); __syncthreads(); }
    }

    // epilogue: fp32 tile ld 132 in smem, fp16 Wh1 write + fused s1
    __syncthreads();
    float* tile = (float*)smem;
    #pragma unroll
    for (int i = 0; i < 2; i++)
        #pragma unroll
        for (int j = 0; j < 4; j++)
            wmma::store_matrix_sync(&tile[(wm * 32 + i * 16) * 132 + wn * 64 + j * 16],
                                    acc[i][j], 132, wmma::mem_row_major);
    __syncthreads();

    #pragma unroll
    for (int t = 0; t < 8; t++) {
        int idx = tid + t * 256;
        int r = idx >> 4, c8 = (idx & 15) * 8;
        if (m0 + r < NN) {
            float4 v0 = *(const float4*)&tile[r * 132 + c8];
            float4 v1 = *(const float4*)&tile[r * 132 + c8 + 4];
            __half2 p0 = __floats2half2_rn(v0.x, v0.y);
            __half2 p1 = __floats2half2_rn(v0.z, v0.w);
            __half2 p2 = __floats2half2_rn(v1.x, v1.y);
            __half2 p3 = __floats2half2_rn(v1.z, v1.w);
            uint4 o = make_uint4(*(uint32_t*)&p0, *(uint32_t*)&p1,
                                 *(uint32_t*)&p2, *(uint32_t*)&p3);
            *(uint4*)&g_Wh1h[(size_t)(m0 + r) * 256 + n0 + c8] = o;
        }
    }
    {
        int hl = tid & 1;
        int row = tid >> 1;
        int hg = (n0 >> 6) + hl;
        const float* rp = &tile[row * 132 + hl * 64];
        float sr = 0.f, sc = 0.f;
        #pragma unroll
        for (int q = 0; q < 16; q++) {
            float4 v  = *(const float4*)&rp[q * 4];
            float4 ar = __ldg((const float4*)&a[hg * 128 + q * 4]);
            float4 ac = __ldg((const float4*)&a[hg * 128 + 64 + q * 4]);
            sr += v.x * ar.x + v.y * ar.y + v.z * ar.z + v.w * ar.w;
            sc += v.x * ac.x + v.y * ac.y + v.z * ac.z + v.w * ac.w;
        }
        int gr = m0 + row;
        if (gr < NN) {
            g_s1r[gr * 4 + hg] = sr;
            g_s1c[gr * 4 + hg] = sc;
        }
    }
}

// ---------------- GEMM2: Wh2 = h16 @ B2 [128x48, K=256, fp16 single-pass, fused s2] ----------------
#define T2_A 0
#define T2_B 34816
#define T2_STAGE 49152
#define T2_BYTES (2 * T2_STAGE)

__global__ __launch_bounds__(256) void k_gemm2(const float* __restrict__ aout) {
    extern __shared__ __align__(16) unsigned char smem[];
    uint32_t sbase = smem_u32(smem);
    int tid = threadIdx.x;
    int m0 = blockIdx.x * 128;

    #pragma unroll
    for (int c = 0; c < 2; c++) {
        uint32_t st = sbase + c * T2_STAGE;
        #pragma unroll
        for (int t = 0; t < 8; t++) {           // A: 2048 chunks (128 rows x 16)
            int idx = tid + t * 256;
            int r = idx >> 4, c16 = idx & 15;
            size_t so = ((size_t)(m0 + r) * 256 + c * 128 + c16 * 8) * 2;
            cpa16(st + T2_A + (uint32_t)(r * 136 + c16 * 8) * 2, (const unsigned char*)g_h16 + so);
        }
        #pragma unroll
        for (int t = 0; t < 3; t++) {           // B: 768 chunks (128 k-rows x 6)
            int idx = tid + t * 256;
            int kr = idx / 6, c6 = idx - kr * 6;
            size_t so = ((size_t)(c * 128 + kr) * 48 + c6 * 8) * 2;
            cpa16(st + T2_B + (uint32_t)(kr * 56 + c6 * 8) * 2, (const unsigned char*)g_B2f + so);
        }
        CP_COMMIT();
    }

    int wid = tid >> 5;                          // warp tile 16 x 48

    wmma::fragment<wmma::accumulator, 16, 16, 16, float> acc[3];
    #pragma unroll
    for (int j = 0; j < 3; j++) wmma::fill_fragment(acc[j], 0.f);

    CP_WAIT1();
    __syncthreads();

    #pragma unroll
    for (int c = 0; c < 2; c++) {
        const unsigned char* st = smem + c * T2_STAGE;
        const __half* A_ = (const __half*)(st + T2_A);
        const __half* B_ = (const __half*)(st + T2_B);
        #pragma unroll
        for (int k16 = 0; k16 < 8; k16++) {
            wmma::fragment<wmma::matrix_a, 16, 16, 16, __half, wmma::row_major> af;
            wmma::fragment<wmma::matrix_b, 16, 16, 16, __half, wmma::row_major> bfr[3];
            wmma::load_matrix_sync(af, A_ + (wid * 16) * 136 + k16 * 16, 136);
            #pragma unroll
            for (int j = 0; j < 3; j++)
                wmma::load_matrix_sync(bfr[j], B_ + (k16 * 16) * 56 + j * 16, 56);
            #pragma unroll
            for (int j = 0; j < 3; j++)
                wmma::mma_sync(acc[j], af, bfr[j], acc[j]);
        }
        if (c == 0) { CP_WAIT0(); __syncthreads(); }
    }

    __syncthreads();
    float* tile = (float*)smem;
    #pragma unroll
    for (int j = 0; j < 3; j++)
        wmma::store_matrix_sync(&tile[(wid * 16) * 56 + j * 16], acc[j], 56, wmma::mem_row_major);
    __syncthreads();

    #pragma unroll
    for (int t = 0; t < 6; t++) {               // fp16 Wh2 store
        int idx = tid + t * 256;
        int r = idx / 12, c4 = idx - r * 12;
        float4 v = *(const float4*)&tile[r * 56 + c4 * 4];
        __half2 p0 = __floats2half2_rn(v.x, v.y);
        __half2 p1 = __floats2half2_rn(v.z, v.w);
        uint2 o = make_uint2(*(uint32_t*)&p0, *(uint32_t*)&p1);
        *(uint2*)&g_Wh2h[(size_t)(m0 + r) * 48 + c4 * 4] = o;
    }
    if (tid < 128) {
        int row = tid;
        const float* rp = &tile[row * 56];
        float sr = 0.f, sc = 0.f;
        #pragma unroll
        for (int q = 0; q < 10; q++) {
            float4 v  = *(const float4*)&rp[q * 4];
            float4 ar = __ldg((const float4*)&aout[q * 4]);
            float4 ac = __ldg((const float4*)&aout[40 + q * 4]);
            sr += v.x * ar.x + v.y * ar.y + v.z * ar.z + v.w * ar.w;
            sc += v.x * ac.x + v.y * ac.y + v.z * ac.z + v.w * ac.w;
        }
        int gr = m0 + row;
        if (gr < NN) { g_s2r[gr] = sr; g_s2c[gr] = sc; }
    }
}

// ---------------- layer1 aggregation: HFMA2 inner loop, 1/64-scaled half2 weights ----------------
__global__ __launch_bounds__(256) void k_gat1() {
    __shared__ __align__(16) __half2 sW[8][32][4];   // per warp, edge slot, head: (ex/64, ex/64)
    __shared__ int sJ[8][32];
    int w = threadIdx.x >> 5;
    int gw = (blockIdx.x * blockDim.x + threadIdx.x) >> 5;
    int lane = threadIdx.x & 31;
    if (gw >= NN) return;
    const float4 sr = *(const float4*)&g_s1r[gw * 4];
    int beg = g_off[gw], end = g_off[gw + 1];
    int hsel = lane >> 3;                         // head owned by this lane (8 cols each)

    __half2 accA0 = __float2half2_rn(0.f), accA1 = accA0, accA2 = accA0, accA3 = accA0;
    __half2 accB0 = accA0, accB1 = accA0, accB2 = accA0, accB3 = accA0;
    float d0 = 0.f, d1 = 0.f, d2 = 0.f, d3 = 0.f;

    for (int base = beg; base < end; base += 32) {
        int e = base + lane;
        int j = 0;
        float4 ex = make_float4(0.f, 0.f, 0.f, 0.f);
        if (e < end) {
            j = __ldg(&g_csr[e]);
            float4 s = __ldg((const float4*)&g_s1c[j * 4]);
            ex.x = __expf(lrelu(sr.x + s.x));
            ex.y = __expf(lrelu(sr.y + s.y));
            ex.z = __expf(lrelu(sr.z + s.z));
            ex.w = __expf(lrelu(sr.w + s.w));
            d0 += ex.x; d1 += ex.y; d2 += ex.z; d3 += ex.w;
        }
        // store scaled half2 weights (16B vectorized)
        {
            __half2 w0 = __floats2half2_rn(ex.x * 0.015625f, ex.x * 0.015625f);
            __half2 w1 = __floats2half2_rn(ex.y * 0.015625f, ex.y * 0.015625f);
            __half2 w2 = __floats2half2_rn(ex.z * 0.015625f, ex.z * 0.015625f);
            __half2 w3 = __floats2half2_rn(ex.w * 0.015625f, ex.w * 0.015625f);
            *(uint4*)&sW[w][lane][0] = make_uint4(*(uint32_t*)&w0, *(uint32_t*)&w1,
                                                  *(uint32_t*)&w2, *(uint32_t*)&w3);
        }
        sJ[w][lane] = j;
        __syncwarp();
        int cnt = min(32, end - base);
        for (int k = 0; k < cnt; k += 2) {
            {
                int jj = sJ[w][k];
                __half2 wt = sW[w][k][hsel];
                uint4 q = __ldg((const uint4*)&g_Wh1h[(size_t)jj * 256 + 8 * lane]);
                accA0 = __hfma2(wt, *(__half2*)&q.x, accA0);
                accA1 = __hfma2(wt, *(__half2*)&q.y, accA1);
                accA2 = __hfma2(wt, *(__half2*)&q.z, accA2);
                accA3 = __hfma2(wt, *(__half2*)&q.w, accA3);
            }
            if (k + 1 < cnt) {
                int jj = sJ[w][k + 1];
                __half2 wt = sW[w][k + 1][hsel];
                uint4 q = __ldg((const uint4*)&g_Wh1h[(size_t)jj * 256 + 8 * lane]);
                accB0 = __hfma2(wt, *(__half2*)&q.x, accB0);
                accB1 = __hfma2(wt, *(__half2*)&q.y, accB1);
                accB2 = __hfma2(wt, *(__half2*)&q.z, accB2);
                accB3 = __hfma2(wt, *(__half2*)&q.w, accB3);
            }
        }
        __syncwarp();
    }
    d0 = wsum(d0); d1 = wsum(d1); d2 = wsum(d2); d3 = wsum(d3);
    // inv includes the 64x rescale of the fp16 accumulators
    float inv = (hsel & 2) ? ((hsel & 1) ? 64.f / d3 : 64.f / d2)
                           : ((hsel & 1) ? 64.f / d1 : 64.f / d0);

    float2 fa0 = __half22float2(accA0), fb0 = __half22float2(accB0);
    float2 fa1 = __half22float2(accA1), fb1 = __half22float2(accB1);
    float2 fa2 = __half22float2(accA2), fb2 = __half22float2(accB2);
    float2 fa3 = __half22float2(accA3), fb3 = __half22float2(accB3);

    __half2 o0 = __floats2half2_rn(elu((fa0.x + fb0.x) * inv), elu((fa0.y + fb0.y) * inv));
    __half2 o1 = __floats2half2_rn(elu((fa1.x + fb1.x) * inv), elu((fa1.y + fb1.y) * inv));
    __half2 o2 = __floats2half2_rn(elu((fa2.x + fb2.x) * inv), elu((fa2.y + fb2.y) * inv));
    __half2 o3 = __floats2half2_rn(elu((fa3.x + fb3.x) * inv), elu((fa3.y + fb3.y) * inv));
    uint4 o = make_uint4(*(uint32_t*)&o0, *(uint32_t*)&o1,
                         *(uint32_t*)&o2, *(uint32_t*)&o3);
    *(uint4*)&g_h16[(size_t)gw * 256 + 8 * lane] = o;
}

// ---------------- layer2 attention + ELU + log_softmax (fp16 gathers) ----------------
__global__ void k_gat2(float* __restrict__ out) {
    int gw = (blockIdx.x * blockDim.x + threadIdx.x) >> 5;
    int lane = threadIdx.x & 31;
    if (gw >= NN) return;
    float s2v = __ldg(&g_s2r[gw]);
    int beg = g_off[gw], end = g_off[gw + 1];
    int half = lane >> 4, sl = lane & 15;

    float4 acc = make_float4(0.f, 0.f, 0.f, 0.f);
    float den = 0.f;
    for (int base = beg; base < end; base += 32) {
        int e = base + lane;
        int j = 0; float ex = 0.f;
        if (e < end) {
            j = __ldg(&g_csr[e]);
            ex = __expf(lrelu(s2v + __ldg(&g_s2c[j])));
            den += ex;
        }
        int cnt = min(32, end - base);
        for (int k = 0; k < cnt; k += 2) {
            int kk = k + half;
            int src = (kk < cnt) ? kk : k;
            int   jj = __shfl_sync(0xffffffffu, j,  src);
            float w  = __shfl_sync(0xffffffffu, ex, src);
            if (kk >= cnt) w = 0.f;
            if (sl < 10) {
                uint2 q = __ldg((const uint2*)&g_Wh2h[(size_t)jj * 48 + 4 * sl]);
                float2 f0 = __half22float2(*(__half2*)&q.x);
                float2 f1 = __half22float2(*(__half2*)&q.y);
                acc.x += w * f0.x; acc.y += w * f0.y; acc.z += w * f1.x; acc.w += w * f1.y;
            }
        }
    }
    acc.x += __shfl_xor_sync(0xffffffffu, acc.x, 16);
    acc.y += __shfl_xor_sync(0xffffffffu, acc.y, 16);
    acc.z += __shfl_xor_sync(0xffffffffu, acc.z, 16);
    acc.w += __shfl_xor_sync(0xffffffffu, acc.w, 16);
    den = wsum(den);
    float inv = 1.f / den;
    bool valid = (lane < 10);
    float o0 = -1e30f, o1 = -1e30f, o2 = -1e30f, o3 = -1e30f;
    if (valid) {
        o0 = elu(acc.x * inv); o1 = elu(acc.y * inv);
        o2 = elu(acc.z * inv); o3 = elu(acc.w * inv);
    }
    float mm = wmax(fmaxf(fmaxf(o0, o1), fmaxf(o2, o3)));
    float se = 0.f;
    if (valid) se = __expf(o0 - mm) + __expf(o1 - mm) + __expf(o2 - mm) + __expf(o3 - mm);
    se = wsum(se);
    float L = mm + logf(se);
    if (valid)
        *(float4*)&out[(size_t)gw * NCLASS + 4 * lane] = make_float4(o0 - L, o1 - L, o2 - L, o3 - L);
}

// ---------------- launch ----------------
extern "C" void kernel_launch(void* const* d_in, const int* in_sizes, int n_in,
                              void* d_out, int out_size) {
    const float* x    = (const float*)d_in[0];
    const float* W    = (const float*)d_in[1];
    const float* a    = (const float*)d_in[2];
    const float* Wout = (const float*)d_in[3];
    const float* aout = (const float*)d_in[4];
    const int*   row  = (const int*)d_in[5];
    const int*   col  = (const int*)d_in[6];
    int E = in_sizes[5];
    float* out = (float*)d_out;

    static cudaStream_t s2 = nullptr;
    static cudaEvent_t evF = nullptr, evJ = nullptr;
    if (!s2) {
        cudaStreamCreateWithFlags(&s2, cudaStreamNonBlocking);
        cudaEventCreateWithFlags(&evF, cudaEventDisableTiming);
        cudaEventCreateWithFlags(&evJ, cudaEventDisableTiming);
        cudaFuncSetAttribute(k_gemm1, cudaFuncAttributeMaxDynamicSharedMemorySize, T1_BYTES);
        cudaFuncSetAttribute(k_gemm2, cudaFuncAttributeMaxDynamicSharedMemorySize, T2_BYTES);
    }

    // fork CSR chain immediately
    cudaEventRecord(evF, 0);
    cudaStreamWaitEvent(s2, evF, 0);
    k_zero <<<(NN + 255) / 256, 256, 0, s2>>>();
    k_count<<<(E + 255) / 256, 256, 0, s2>>>(row, E);

    k_prep<<<1280, 256>>>(x, W, Wout);
    k_gemm1<<<dim3(NTILE, 2), 256, T1_BYTES>>>(a);     // profiled slot

    k_scan1<<<NB1, SB, 0, s2>>>();
    k_scan2<<<1, 256, 0, s2>>>();
    k_scan3<<<NB1, SB, 0, s2>>>(E);
    k_fill <<<(E + 255) / 256, 256, 0, s2>>>(row, col, E);

    cudaEventRecord(evJ, s2);
    cudaStreamWaitEvent(0, evJ, 0);

    k_gat1<<<(NN + 7) / 8, 256>>>();
    k_gemm2<<<NTILE, 256, T2_BYTES>>>(aout);
    k_gat2<<<(NN + 7) / 8, 256>>>(out);
}